// round 4
// baseline (speedup 1.0000x reference)
#include <cuda_runtime.h>
#include <math.h>

#define NN 100000
#define EE 1600000
#define F_IN 512
#define FF1 64
#define DD2 40
#define NB_SCAN 98   // ceil(NN/1024)

// ---------------- scratch ----------------
__device__ float g_hs1[NN * FF1];
__device__ float g_hd1[NN * FF1];
__device__ float g_h1[NN * FF1];
__device__ float g_hs2[NN * DD2];
__device__ float g_hd2[NN * DD2];
__device__ int   g_deg[NN];
__device__ int   g_incl[NN];
__device__ int   g_rs[NN + 1];
__device__ int   g_cur[NN];
__device__ int   g_bsum[NB_SCAN];
__device__ int   g_csrc[EE];

// ---------------- PTX helpers ----------------
__device__ __forceinline__ unsigned f2tf32(float f) {
    unsigned u;
    asm("cvt.rna.tf32.f32 %0, %1;" : "=r"(u) : "f"(f));
    return u;
}
__device__ __forceinline__ void mma_tf32(float* acc, const unsigned* a, const unsigned* b) {
    asm volatile(
        "mma.sync.aligned.m16n8k8.row.col.f32.tf32.tf32.f32 "
        "{%0,%1,%2,%3}, {%4,%5,%6,%7}, {%8,%9}, {%0,%1,%2,%3};"
        : "+f"(acc[0]), "+f"(acc[1]), "+f"(acc[2]), "+f"(acc[3])
        : "r"(a[0]), "r"(a[1]), "r"(a[2]), "r"(a[3]), "r"(b[0]), "r"(b[1]));
}

// ================= CSR build =================
__global__ void k_hist(const int* __restrict__ dst, int* __restrict__ deg) {
    int i = blockIdx.x * blockDim.x + threadIdx.x;   // EE exact
    atomicAdd(&deg[dst[i]], 1);
}

__global__ void k_scan_block(const int* __restrict__ deg, int* __restrict__ incl,
                             int* __restrict__ bsum) {
    int i = blockIdx.x * 1024 + threadIdx.x;
    int v = (i < NN) ? deg[i] : 0;
    int lane = threadIdx.x & 31, wid = threadIdx.x >> 5;
    int x = v;
#pragma unroll
    for (int o = 1; o < 32; o <<= 1) {
        int y = __shfl_up_sync(0xffffffffu, x, o);
        if (lane >= o) x += y;
    }
    __shared__ int ws[32];
    if (lane == 31) ws[wid] = x;
    __syncthreads();
    if (wid == 0) {
        int y = ws[lane];
#pragma unroll
        for (int o = 1; o < 32; o <<= 1) {
            int z = __shfl_up_sync(0xffffffffu, y, o);
            if (lane >= o) y += z;
        }
        ws[lane] = y;
    }
    __syncthreads();
    if (wid > 0) x += ws[wid - 1];
    if (i < NN) incl[i] = x;
    if (threadIdx.x == 1023) bsum[blockIdx.x] = x;
}

__global__ void k_scan_tops(int* __restrict__ bsum) {
    if (threadIdx.x == 0) {
        int run = 0;
        for (int b = 0; b < NB_SCAN; b++) { int t = bsum[b]; bsum[b] = run; run += t; }
    }
}

__global__ void k_scan_final(const int* __restrict__ deg, const int* __restrict__ incl,
                             const int* __restrict__ bsum,
                             int* __restrict__ rs, int* __restrict__ cur) {
    int i = blockIdx.x * 1024 + threadIdx.x;
    if (i < NN) {
        int ex = bsum[i >> 10] + incl[i] - deg[i];
        rs[i] = ex;
        cur[i] = ex;
    }
    if (i == 0) rs[NN] = EE;
}

__global__ void k_fill_csr(const int* __restrict__ src, const int* __restrict__ dst,
                           int* __restrict__ cur, int* __restrict__ csrc) {
    int e = blockIdx.x * blockDim.x + threadIdx.x;   // EE exact
    int t = dst[e];
    int pos = atomicAdd(&cur[t], 1);
    csrc[pos] = src[e];
}

// ================= layer-1 GEMM: tf32 mma =================
#define APAD 20
#define BPAD 132
__global__ __launch_bounds__(256, 1)
void k_gemm1_mma(const float* __restrict__ A,
                 const float* __restrict__ W1, const float* __restrict__ b1,
                 const float* __restrict__ W2, const float* __restrict__ b2,
                 float* __restrict__ C1, float* __restrict__ C2) {
    __shared__ unsigned As[2][128 * APAD];
    __shared__ unsigned Bs[2][16 * BPAD];

    const int tid = threadIdx.x;
    const int lane = tid & 31;
    const int warp = tid >> 5;
    const int wr = warp & 1;
    const int wc = warp >> 1;
    const int g = lane >> 2;
    const int tg = lane & 3;
    const int row0 = blockIdx.x * 128;

    float acc[4][4][4];
#pragma unroll
    for (int mi = 0; mi < 4; mi++)
#pragma unroll
        for (int ni = 0; ni < 4; ni++)
#pragma unroll
            for (int r = 0; r < 4; r++) acc[mi][ni][r] = 0.f;

    float4 aR[2], bR[2];
    const int fA0 = tid, fA1 = tid + 256;
    const int rA0 = fA0 >> 2, qA0 = fA0 & 3;
    const int rA1 = fA1 >> 2, qA1 = fA1 & 3;
    const int kB0 = fA0 >> 5, cB0 = (fA0 & 31) * 4;
    const int kB1 = fA1 >> 5, cB1 = (fA1 & 31) * 4;

    auto loadA = [&](int kc) {
        int r0g = row0 + rA0, r1g = row0 + rA1;
        aR[0] = (r0g < NN) ? *reinterpret_cast<const float4*>(A + (size_t)r0g * F_IN + kc + qA0 * 4)
                           : make_float4(0.f, 0.f, 0.f, 0.f);
        aR[1] = (r1g < NN) ? *reinterpret_cast<const float4*>(A + (size_t)r1g * F_IN + kc + qA1 * 4)
                           : make_float4(0.f, 0.f, 0.f, 0.f);
    };
    auto loadB = [&](int kc) {
        const float* s0 = (cB0 < 64) ? (W1 + (kc + kB0) * 64 + cB0) : (W2 + (kc + kB0) * 64 + cB0 - 64);
        const float* s1 = (cB1 < 64) ? (W1 + (kc + kB1) * 64 + cB1) : (W2 + (kc + kB1) * 64 + cB1 - 64);
        bR[0] = *reinterpret_cast<const float4*>(s0);
        bR[1] = *reinterpret_cast<const float4*>(s1);
    };
    auto storeA = [&](int buf) {
        uint4 u0 = make_uint4(f2tf32(aR[0].x), f2tf32(aR[0].y), f2tf32(aR[0].z), f2tf32(aR[0].w));
        uint4 u1 = make_uint4(f2tf32(aR[1].x), f2tf32(aR[1].y), f2tf32(aR[1].z), f2tf32(aR[1].w));
        *reinterpret_cast<uint4*>(&As[buf][rA0 * APAD + qA0 * 4]) = u0;
        *reinterpret_cast<uint4*>(&As[buf][rA1 * APAD + qA1 * 4]) = u1;
    };
    auto storeB = [&](int buf) {
        uint4 u0 = make_uint4(f2tf32(bR[0].x), f2tf32(bR[0].y), f2tf32(bR[0].z), f2tf32(bR[0].w));
        uint4 u1 = make_uint4(f2tf32(bR[1].x), f2tf32(bR[1].y), f2tf32(bR[1].z), f2tf32(bR[1].w));
        *reinterpret_cast<uint4*>(&Bs[buf][kB0 * BPAD + cB0]) = u0;
        *reinterpret_cast<uint4*>(&Bs[buf][kB1 * BPAD + cB1]) = u1;
    };

    loadA(0); loadB(0);
    storeA(0); storeB(0);
    int buf = 0;

    const int NITER = F_IN / 16;
    for (int it = 0; it < NITER; it++) {
        __syncthreads();
        if (it + 1 < NITER) { loadA((it + 1) * 16); loadB((it + 1) * 16); }

#pragma unroll
        for (int ks = 0; ks < 2; ks++) {
            const int k0 = ks * 8;
            unsigned afr[4][4], bfr[4][2];
#pragma unroll
            for (int mi = 0; mi < 4; mi++) {
                int base = wr * 64 + mi * 16;
                afr[mi][0] = As[buf][(base + g) * APAD + k0 + tg];
                afr[mi][1] = As[buf][(base + g + 8) * APAD + k0 + tg];
                afr[mi][2] = As[buf][(base + g) * APAD + k0 + tg + 4];
                afr[mi][3] = As[buf][(base + g + 8) * APAD + k0 + tg + 4];
            }
#pragma unroll
            for (int ni = 0; ni < 4; ni++) {
                int col = wc * 32 + ni * 8 + g;
                bfr[ni][0] = Bs[buf][(k0 + tg) * BPAD + col];
                bfr[ni][1] = Bs[buf][(k0 + tg + 4) * BPAD + col];
            }
#pragma unroll
            for (int mi = 0; mi < 4; mi++)
#pragma unroll
                for (int ni = 0; ni < 4; ni++)
                    mma_tf32(acc[mi][ni], afr[mi], bfr[ni]);
        }
        if (it + 1 < NITER) { storeA(buf ^ 1); storeB(buf ^ 1); buf ^= 1; }
    }

    float* Cw = (wc < 2) ? C1 : C2;
    const float* bw = (wc < 2) ? b1 : b2;
    const int cbase = (wc < 2) ? wc * 32 : (wc - 2) * 32;
#pragma unroll
    for (int mi = 0; mi < 4; mi++) {
#pragma unroll
        for (int ni = 0; ni < 4; ni++) {
            int col = cbase + ni * 8 + 2 * tg;
            float bb0 = __ldg(bw + col), bb1 = __ldg(bw + col + 1);
            int r0 = row0 + wr * 64 + mi * 16 + g;
            int r1 = r0 + 8;
            if (r0 < NN) {
                float2 v = make_float2(acc[mi][ni][0] + bb0, acc[mi][ni][1] + bb1);
                *reinterpret_cast<float2*>(Cw + (size_t)r0 * 64 + col) = v;
            }
            if (r1 < NN) {
                float2 v = make_float2(acc[mi][ni][2] + bb0, acc[mi][ni][3] + bb1);
                *reinterpret_cast<float2*>(Cw + (size_t)r1 * 64 + col) = v;
            }
        }
    }
}

// ================= layer-2 GEMM (FFMA, K=64, M=40) =================
__global__ void k_gemm_dual(const float* __restrict__ A, int K, int M,
                            const float* __restrict__ W1, const float* __restrict__ b1,
                            const float* __restrict__ W2, const float* __restrict__ b2,
                            float* __restrict__ C1, float* __restrict__ C2) {
    __shared__ float xs[32][16];
    __shared__ float w1s[16][64];
    __shared__ float w2s[16][64];
    const int tx = threadIdx.x;
    const int ty = threadIdx.y;
    const int tid = ty * 64 + tx;
    const int row0 = blockIdx.x * 32;

    float acc1[8], acc2[8];
#pragma unroll
    for (int r = 0; r < 8; r++) { acc1[r] = 0.f; acc2[r] = 0.f; }

    for (int kc = 0; kc < K; kc += 16) {
        for (int i = tid; i < 32 * 16; i += 256) {
            int r = i >> 4, k = i & 15;
            xs[r][k] = A[(row0 + r) * K + kc + k];
        }
        for (int i = tid; i < 16 * 64; i += 256) {
            int k = i >> 6, c = i & 63;
            float v1 = 0.f, v2 = 0.f;
            if (c < M) { v1 = W1[(kc + k) * M + c]; v2 = W2[(kc + k) * M + c]; }
            w1s[k][c] = v1; w2s[k][c] = v2;
        }
        __syncthreads();
#pragma unroll
        for (int kk = 0; kk < 16; kk++) {
            float w1 = w1s[kk][tx], w2 = w2s[kk][tx];
#pragma unroll
            for (int r = 0; r < 8; r++) {
                float a = xs[ty * 8 + r][kk];
                acc1[r] = fmaf(a, w1, acc1[r]);
                acc2[r] = fmaf(a, w2, acc2[r]);
            }
        }
        __syncthreads();
    }

    if (tx < M) {
        float bb1 = b1[tx], bb2 = b2[tx];
#pragma unroll
        for (int r = 0; r < 8; r++) {
            int row = row0 + ty * 8 + r;
            C1[row * M + tx] = acc1[r] + bb1;
            C2[row * M + tx] = acc2[r] + bb2;
        }
    }
}

// ================= fused layer-1 aggregation: one warp per dst node =================
// lane holds feats {2*lane, 2*lane+1}; head = lane>>2 (8 dims = 4 lanes/head)
__global__ __launch_bounds__(256)
void k_agg1(const float* __restrict__ hs, const float* __restrict__ hd,
            const float* __restrict__ attn,
            const int* __restrict__ rs, const int* __restrict__ csrc,
            float* __restrict__ out) {
    int t = blockIdx.x * 8 + (threadIdx.x >> 5);      // 12500*8 = NN exact
    int lane = threadIdx.x & 31;
    int beg = rs[t], end = rs[t + 1];

    float2 hdv = *reinterpret_cast<const float2*>(hd + (size_t)t * 64 + lane * 2);
    float2 av  = __ldg(reinterpret_cast<const float2*>(attn + lane * 2));

    float acc0 = 0.f, acc1 = 0.f, s = 0.f;

    // pipeline: src idx at distance 2, gather at distance 1
    int sn1 = (beg < end) ? __ldg(csrc + beg) : 0;
    int sn2 = (beg + 1 < end) ? __ldg(csrc + beg + 1) : 0;
    float2 h0 = (beg < end)
        ? __ldg(reinterpret_cast<const float2*>(hs + (size_t)sn1 * 64 + lane * 2))
        : make_float2(0.f, 0.f);

    for (int i = beg; i < end; i++) {
        int sn_next = sn2;
        sn2 = (i + 2 < end) ? __ldg(csrc + i + 2) : 0;
        float2 h1v = (i + 1 < end)
            ? __ldg(reinterpret_cast<const float2*>(hs + (size_t)sn_next * 64 + lane * 2))
            : make_float2(0.f, 0.f);

        float x0 = h0.x + hdv.x; x0 = x0 > 0.f ? x0 : 0.2f * x0;
        float x1 = h0.y + hdv.y; x1 = x1 > 0.f ? x1 : 0.2f * x1;
        float part = fmaf(x0, av.x, x1 * av.y);
        part += __shfl_xor_sync(0xffffffffu, part, 1);
        part += __shfl_xor_sync(0xffffffffu, part, 2);
        float p = __expf(part);
        acc0 = fmaf(p, h0.x, acc0);
        acc1 = fmaf(p, h0.y, acc1);
        s += p;

        h0 = h1v;
    }

    float inv = 1.f / (s + 1e-9f);
    float o0 = acc0 * inv, o1 = acc1 * inv;
    o0 = o0 > 0.f ? o0 : (__expf(o0) - 1.f);      // fused ELU
    o1 = o1 > 0.f ? o1 : (__expf(o1) - 1.f);
    *reinterpret_cast<float2*>(out + (size_t)t * 64 + lane * 2) = make_float2(o0, o1);
}

// ================= fused layer-2 aggregation (D=40, lanes 0..19 hold float2) ========
__global__ __launch_bounds__(256)
void k_agg2(const float* __restrict__ hs, const float* __restrict__ hd,
            const float* __restrict__ attn,
            const int* __restrict__ rs, const int* __restrict__ csrc,
            float* __restrict__ out) {
    int t = blockIdx.x * 8 + (threadIdx.x >> 5);
    int lane = threadIdx.x & 31;
    bool act = lane < 20;
    int beg = rs[t], end = rs[t + 1];

    float2 hdv = act ? *reinterpret_cast<const float2*>(hd + (size_t)t * 40 + lane * 2)
                     : make_float2(0.f, 0.f);
    float2 av  = act ? __ldg(reinterpret_cast<const float2*>(attn + lane * 2))
                     : make_float2(0.f, 0.f);

    float acc0 = 0.f, acc1 = 0.f, s = 0.f;

    int sn1 = (beg < end) ? __ldg(csrc + beg) : 0;
    int sn2 = (beg + 1 < end) ? __ldg(csrc + beg + 1) : 0;
    float2 h0 = (act && beg < end)
        ? __ldg(reinterpret_cast<const float2*>(hs + (size_t)sn1 * 40 + lane * 2))
        : make_float2(0.f, 0.f);

    for (int i = beg; i < end; i++) {
        int sn_next = sn2;
        sn2 = (i + 2 < end) ? __ldg(csrc + i + 2) : 0;
        float2 h1v = (act && i + 1 < end)
            ? __ldg(reinterpret_cast<const float2*>(hs + (size_t)sn_next * 40 + lane * 2))
            : make_float2(0.f, 0.f);

        float x0 = h0.x + hdv.x; x0 = x0 > 0.f ? x0 : 0.2f * x0;
        float x1 = h0.y + hdv.y; x1 = x1 > 0.f ? x1 : 0.2f * x1;
        float part = fmaf(x0, av.x, x1 * av.y);       // 0 for inactive lanes
#pragma unroll
        for (int o = 16; o > 0; o >>= 1)
            part += __shfl_xor_sync(0xffffffffu, part, o);
        float p = __expf(part);
        acc0 = fmaf(p, h0.x, acc0);
        acc1 = fmaf(p, h0.y, acc1);
        s += p;

        h0 = h1v;
    }

    if (act) {
        float inv = 1.f / (s + 1e-9f);
        *reinterpret_cast<float2*>(out + (size_t)t * 40 + lane * 2) =
            make_float2(acc0 * inv, acc1 * inv);
    }
}

// ================= launch =================
extern "C" void kernel_launch(void* const* d_in, const int* in_sizes, int n_in,
                              void* d_out, int out_size) {
    const float* x   = (const float*)d_in[0];
    const int*   src = (const int*)d_in[1];
    const int*   dst = (const int*)d_in[2];
    const float* W1s = (const float*)d_in[3];
    const float* b1s = (const float*)d_in[4];
    const float* W1d = (const float*)d_in[5];
    const float* b1d = (const float*)d_in[6];
    const float* a1  = (const float*)d_in[7];
    const float* W2s = (const float*)d_in[8];
    const float* b2s = (const float*)d_in[9];
    const float* W2d = (const float*)d_in[10];
    const float* b2d = (const float*)d_in[11];
    const float* a2  = (const float*)d_in[12];
    float* out = (float*)d_out;

    float *hs1, *hd1, *h1, *hs2, *hd2;
    int *deg, *incl, *rs, *cur, *bsum, *csrc;
    cudaGetSymbolAddress((void**)&hs1, g_hs1);
    cudaGetSymbolAddress((void**)&hd1, g_hd1);
    cudaGetSymbolAddress((void**)&h1,  g_h1);
    cudaGetSymbolAddress((void**)&hs2, g_hs2);
    cudaGetSymbolAddress((void**)&hd2, g_hd2);
    cudaGetSymbolAddress((void**)&deg, g_deg);
    cudaGetSymbolAddress((void**)&incl, g_incl);
    cudaGetSymbolAddress((void**)&rs,  g_rs);
    cudaGetSymbolAddress((void**)&cur, g_cur);
    cudaGetSymbolAddress((void**)&bsum, g_bsum);
    cudaGetSymbolAddress((void**)&csrc, g_csrc);

    const int T = 256;

    // ---- CSR build (shared by both layers) + layer-1 GEMM (independent) ----
    cudaMemsetAsync(deg, 0, NN * sizeof(int));
    k_hist<<<EE / T, T>>>(dst, deg);
    k_gemm1_mma<<<(NN + 127) / 128, 256>>>(x, W1s, b1s, W1d, b1d, hs1, hd1);
    k_scan_block<<<NB_SCAN, 1024>>>(deg, incl, bsum);
    k_scan_tops<<<1, 32>>>(bsum);
    k_scan_final<<<NB_SCAN, 1024>>>(deg, incl, bsum, rs, cur);
    k_fill_csr<<<EE / T, T>>>(src, dst, cur, csrc);

    // ---- layer 1 fused aggregation (+ELU) ----
    k_agg1<<<NN / 8, T>>>(hs1, hd1, a1, rs, csrc, h1);

    // ---- layer 2 ----
    k_gemm_dual<<<NN / 32, dim3(64, 4)>>>(h1, FF1, DD2, W2s, b2s, W2d, b2d, hs2, hd2);
    k_agg2<<<NN / 8, T>>>(hs2, hd2, a2, rs, csrc, out);
}

// round 6
// speedup vs baseline: 1.2519x; 1.2519x over previous
#include <cuda_runtime.h>
#include <math.h>

#define NN 100000
#define EE 1600000
#define F_IN 512
#define FF1 64
#define DD2 40

// ---------------- scratch ----------------
__device__ float g_hs1[NN * FF1];
__device__ float g_hd1[NN * FF1];
__device__ float g_s1[NN * 8];
__device__ float g_h1[NN * FF1];
__device__ float g_hs2[NN * DD2];
__device__ float g_hd2[NN * DD2];
__device__ float g_s2[NN];

// ---------------- PTX helpers ----------------
__device__ __forceinline__ unsigned f2tf32(float f) {
    unsigned u;
    asm("cvt.rna.tf32.f32 %0, %1;" : "=r"(u) : "f"(f));
    return u;
}
__device__ __forceinline__ void redv4(float* addr, float a, float b, float c, float d) {
    asm volatile("red.global.add.v4.f32 [%0], {%1,%2,%3,%4};"
                 :: "l"(addr), "f"(a), "f"(b), "f"(c), "f"(d) : "memory");
}
__device__ __forceinline__ void red1(float* addr, float a) {
    asm volatile("red.global.add.f32 [%0], %1;" :: "l"(addr), "f"(a) : "memory");
}
__device__ __forceinline__ void mma_tf32(float* acc, const unsigned* a, const unsigned* b) {
    asm volatile(
        "mma.sync.aligned.m16n8k8.row.col.f32.tf32.tf32.f32 "
        "{%0,%1,%2,%3}, {%4,%5,%6,%7}, {%8,%9}, {%0,%1,%2,%3};"
        : "+f"(acc[0]), "+f"(acc[1]), "+f"(acc[2]), "+f"(acc[3])
        : "r"(a[0]), "r"(a[1]), "r"(a[2]), "r"(a[3]), "r"(b[0]), "r"(b[1]));
}

// ---------------- zero kernels ----------------
__global__ void k_zero2(float* a, int na, float* b, int nb) {
    int i = blockIdx.x * blockDim.x + threadIdx.x;
    if (i < na) a[i] = 0.f;
    if (i < nb) b[i] = 0.f;
}
__global__ void k_zero1(float* a, int na) {
    int i = blockIdx.x * blockDim.x + threadIdx.x;
    if (i < na) a[i] = 0.f;
}

// ================= layer-1 GEMM: tf32 mma (launch position 4 -> profiled) =========
#define APAD 20
#define BPAD 132
__global__ __launch_bounds__(256, 1)
void k_gemm1_mma(const float* __restrict__ A,
                 const float* __restrict__ W1, const float* __restrict__ b1,
                 const float* __restrict__ W2, const float* __restrict__ b2,
                 float* __restrict__ C1, float* __restrict__ C2) {
    __shared__ unsigned As[2][128 * APAD];
    __shared__ unsigned Bs[2][16 * BPAD];

    const int tid = threadIdx.x;
    const int lane = tid & 31;
    const int warp = tid >> 5;
    const int wr = warp & 1;
    const int wc = warp >> 1;
    const int g = lane >> 2;
    const int tg = lane & 3;
    const int row0 = blockIdx.x * 128;

    float acc[4][4][4];
#pragma unroll
    for (int mi = 0; mi < 4; mi++)
#pragma unroll
        for (int ni = 0; ni < 4; ni++)
#pragma unroll
            for (int r = 0; r < 4; r++) acc[mi][ni][r] = 0.f;

    float4 aR[2], bR[2];
    const int fA0 = tid, fA1 = tid + 256;
    const int rA0 = fA0 >> 2, qA0 = fA0 & 3;
    const int rA1 = fA1 >> 2, qA1 = fA1 & 3;
    const int kB0 = fA0 >> 5, cB0 = (fA0 & 31) * 4;
    const int kB1 = fA1 >> 5, cB1 = (fA1 & 31) * 4;

    auto loadA = [&](int kc) {
        int r0g = row0 + rA0, r1g = row0 + rA1;
        aR[0] = (r0g < NN) ? *reinterpret_cast<const float4*>(A + (size_t)r0g * F_IN + kc + qA0 * 4)
                           : make_float4(0.f, 0.f, 0.f, 0.f);
        aR[1] = (r1g < NN) ? *reinterpret_cast<const float4*>(A + (size_t)r1g * F_IN + kc + qA1 * 4)
                           : make_float4(0.f, 0.f, 0.f, 0.f);
    };
    auto loadB = [&](int kc) {
        const float* s0 = (cB0 < 64) ? (W1 + (kc + kB0) * 64 + cB0) : (W2 + (kc + kB0) * 64 + cB0 - 64);
        const float* s1 = (cB1 < 64) ? (W1 + (kc + kB1) * 64 + cB1) : (W2 + (kc + kB1) * 64 + cB1 - 64);
        bR[0] = *reinterpret_cast<const float4*>(s0);
        bR[1] = *reinterpret_cast<const float4*>(s1);
    };
    auto storeA = [&](int buf) {
        uint4 u0 = make_uint4(f2tf32(aR[0].x), f2tf32(aR[0].y), f2tf32(aR[0].z), f2tf32(aR[0].w));
        uint4 u1 = make_uint4(f2tf32(aR[1].x), f2tf32(aR[1].y), f2tf32(aR[1].z), f2tf32(aR[1].w));
        *reinterpret_cast<uint4*>(&As[buf][rA0 * APAD + qA0 * 4]) = u0;
        *reinterpret_cast<uint4*>(&As[buf][rA1 * APAD + qA1 * 4]) = u1;
    };
    auto storeB = [&](int buf) {
        uint4 u0 = make_uint4(f2tf32(bR[0].x), f2tf32(bR[0].y), f2tf32(bR[0].z), f2tf32(bR[0].w));
        uint4 u1 = make_uint4(f2tf32(bR[1].x), f2tf32(bR[1].y), f2tf32(bR[1].z), f2tf32(bR[1].w));
        *reinterpret_cast<uint4*>(&Bs[buf][kB0 * BPAD + cB0]) = u0;
        *reinterpret_cast<uint4*>(&Bs[buf][kB1 * BPAD + cB1]) = u1;
    };

    loadA(0); loadB(0);
    storeA(0); storeB(0);
    int buf = 0;

    const int NITER = F_IN / 16;
    for (int it = 0; it < NITER; it++) {
        __syncthreads();
        if (it + 1 < NITER) { loadA((it + 1) * 16); loadB((it + 1) * 16); }

#pragma unroll
        for (int ks = 0; ks < 2; ks++) {
            const int k0 = ks * 8;
            unsigned afr[4][4], bfr[4][2];
#pragma unroll
            for (int mi = 0; mi < 4; mi++) {
                int base = wr * 64 + mi * 16;
                afr[mi][0] = As[buf][(base + g) * APAD + k0 + tg];
                afr[mi][1] = As[buf][(base + g + 8) * APAD + k0 + tg];
                afr[mi][2] = As[buf][(base + g) * APAD + k0 + tg + 4];
                afr[mi][3] = As[buf][(base + g + 8) * APAD + k0 + tg + 4];
            }
#pragma unroll
            for (int ni = 0; ni < 4; ni++) {
                int col = wc * 32 + ni * 8 + g;
                bfr[ni][0] = Bs[buf][(k0 + tg) * BPAD + col];
                bfr[ni][1] = Bs[buf][(k0 + tg + 4) * BPAD + col];
            }
#pragma unroll
            for (int mi = 0; mi < 4; mi++)
#pragma unroll
                for (int ni = 0; ni < 4; ni++)
                    mma_tf32(acc[mi][ni], afr[mi], bfr[ni]);
        }
        if (it + 1 < NITER) { storeA(buf ^ 1); storeB(buf ^ 1); buf ^= 1; }
    }

    float* Cw = (wc < 2) ? C1 : C2;
    const float* bw = (wc < 2) ? b1 : b2;
    const int cbase = (wc < 2) ? wc * 32 : (wc - 2) * 32;
#pragma unroll
    for (int mi = 0; mi < 4; mi++) {
#pragma unroll
        for (int ni = 0; ni < 4; ni++) {
            int col = cbase + ni * 8 + 2 * tg;
            float bb0 = __ldg(bw + col), bb1 = __ldg(bw + col + 1);
            int r0 = row0 + wr * 64 + mi * 16 + g;
            int r1 = r0 + 8;
            if (r0 < NN) {
                float2 v = make_float2(acc[mi][ni][0] + bb0, acc[mi][ni][1] + bb1);
                *reinterpret_cast<float2*>(Cw + (size_t)r0 * 64 + col) = v;
            }
            if (r1 < NN) {
                float2 v = make_float2(acc[mi][ni][2] + bb0, acc[mi][ni][3] + bb1);
                *reinterpret_cast<float2*>(Cw + (size_t)r1 * 64 + col) = v;
            }
        }
    }
}

// ================= layer-2 GEMM (FFMA, K=64, M=40) =================
__global__ void k_gemm_dual(const float* __restrict__ A, int K, int M,
                            const float* __restrict__ W1, const float* __restrict__ b1,
                            const float* __restrict__ W2, const float* __restrict__ b2,
                            float* __restrict__ C1, float* __restrict__ C2) {
    __shared__ float xs[32][16];
    __shared__ float w1s[16][64];
    __shared__ float w2s[16][64];
    const int tx = threadIdx.x;
    const int ty = threadIdx.y;
    const int tid = ty * 64 + tx;
    const int row0 = blockIdx.x * 32;

    float acc1[8], acc2[8];
#pragma unroll
    for (int r = 0; r < 8; r++) { acc1[r] = 0.f; acc2[r] = 0.f; }

    for (int kc = 0; kc < K; kc += 16) {
        for (int i = tid; i < 32 * 16; i += 256) {
            int r = i >> 4, k = i & 15;
            xs[r][k] = A[(row0 + r) * K + kc + k];
        }
        for (int i = tid; i < 16 * 64; i += 256) {
            int k = i >> 6, c = i & 63;
            float v1 = 0.f, v2 = 0.f;
            if (c < M) { v1 = W1[(kc + k) * M + c]; v2 = W2[(kc + k) * M + c]; }
            w1s[k][c] = v1; w2s[k][c] = v2;
        }
        __syncthreads();
#pragma unroll
        for (int kk = 0; kk < 16; kk++) {
            float w1 = w1s[kk][tx], w2 = w2s[kk][tx];
#pragma unroll
            for (int r = 0; r < 8; r++) {
                float a = xs[ty * 8 + r][kk];
                acc1[r] = fmaf(a, w1, acc1[r]);
                acc2[r] = fmaf(a, w2, acc2[r]);
            }
        }
        __syncthreads();
    }

    if (tx < M) {
        float bb1 = b1[tx], bb2 = b2[tx];
#pragma unroll
        for (int r = 0; r < 8; r++) {
            int row = row0 + ty * 8 + r;
            C1[row * M + tx] = acc1[r] + bb1;
            C2[row * M + tx] = acc2[r] + bb2;
        }
    }
}

// ========== fused layer-1 edge pass: gather once, RED p and p*hs ==========
__global__ __launch_bounds__(256)
void k_edge_agg1(const float* __restrict__ hs, const float* __restrict__ hd,
                 const float* __restrict__ attn,
                 const int* __restrict__ src, const int* __restrict__ dst,
                 float* __restrict__ s, float* __restrict__ acc) {
    int idx = blockIdx.x * blockDim.x + threadIdx.x;   // EE*8 exact
    int e = idx >> 3, h = idx & 7;
    int sn = __ldg(src + e), tn = __ldg(dst + e);
    const float4* a = reinterpret_cast<const float4*>(hs + (size_t)sn * 64 + h * 8);
    const float4* b = reinterpret_cast<const float4*>(hd + (size_t)tn * 64 + h * 8);
    const float4* w = reinterpret_cast<const float4*>(attn + h * 8);
    float4 a0 = a[0], a1 = a[1];
    float4 b0 = b[0], b1 = b[1];
    float4 w0 = __ldg(&w[0]), w1 = __ldg(&w[1]);

    float lg = 0.f, x;
    x = a0.x + b0.x; lg = fmaf((x > 0.f ? x : 0.2f * x), w0.x, lg);
    x = a0.y + b0.y; lg = fmaf((x > 0.f ? x : 0.2f * x), w0.y, lg);
    x = a0.z + b0.z; lg = fmaf((x > 0.f ? x : 0.2f * x), w0.z, lg);
    x = a0.w + b0.w; lg = fmaf((x > 0.f ? x : 0.2f * x), w0.w, lg);
    x = a1.x + b1.x; lg = fmaf((x > 0.f ? x : 0.2f * x), w1.x, lg);
    x = a1.y + b1.y; lg = fmaf((x > 0.f ? x : 0.2f * x), w1.y, lg);
    x = a1.z + b1.z; lg = fmaf((x > 0.f ? x : 0.2f * x), w1.z, lg);
    x = a1.w + b1.w; lg = fmaf((x > 0.f ? x : 0.2f * x), w1.w, lg);

    float p = __expf(lg);

    float* o = acc + (size_t)tn * 64 + h * 8;
    redv4(o,     p * a0.x, p * a0.y, p * a0.z, p * a0.w);
    redv4(o + 4, p * a1.x, p * a1.y, p * a1.z, p * a1.w);

    float p1 = __shfl_down_sync(0xffffffffu, p, 1);
    float p2 = __shfl_down_sync(0xffffffffu, p, 2);
    float p3 = __shfl_down_sync(0xffffffffu, p, 3);
    if ((h & 3) == 0)
        redv4(s + (size_t)tn * 8 + h, p, p1, p2, p3);
}

// ---- scale1: h1 = elu(acc / (s + eps)), float4 granularity ----
__global__ void k_scale1(float* __restrict__ acc, const float* __restrict__ s) {
    int i = blockIdx.x * blockDim.x + threadIdx.x;
    if (i >= NN * 16) return;
    int t = i >> 4, q = i & 15;
    float inv = 1.f / (__ldg(s + t * 8 + (q >> 1)) + 1e-9f);
    float4 v = *reinterpret_cast<float4*>(acc + (size_t)t * 64 + q * 4);
    v.x *= inv; v.y *= inv; v.z *= inv; v.w *= inv;
    v.x = v.x > 0.f ? v.x : (__expf(v.x) - 1.f);
    v.y = v.y > 0.f ? v.y : (__expf(v.y) - 1.f);
    v.z = v.z > 0.f ? v.z : (__expf(v.z) - 1.f);
    v.w = v.w > 0.f ? v.w : (__expf(v.w) - 1.f);
    *reinterpret_cast<float4*>(acc + (size_t)t * 64 + q * 4) = v;
}

// ========== fused layer-2 edge pass: 8 threads/edge, D=40 ==========
__global__ __launch_bounds__(256)
void k_edge_agg2(const float* __restrict__ hs, const float* __restrict__ hd,
                 const float* __restrict__ attn,
                 const int* __restrict__ src, const int* __restrict__ dst,
                 float* __restrict__ s, float* __restrict__ out) {
    int idx = blockIdx.x * blockDim.x + threadIdx.x;   // EE*8 exact
    int e = idx >> 3, j = idx & 7;
    int sn = __ldg(src + e), tn = __ldg(dst + e);

    float4 av[2], bv[2], wv[2];
    bool act2 = (j < 2);
    av[0] = *reinterpret_cast<const float4*>(hs + (size_t)sn * 40 + j * 4);
    bv[0] = *reinterpret_cast<const float4*>(hd + (size_t)tn * 40 + j * 4);
    wv[0] = __ldg(reinterpret_cast<const float4*>(attn + j * 4));
    if (act2) {
        av[1] = *reinterpret_cast<const float4*>(hs + (size_t)sn * 40 + (j + 8) * 4);
        bv[1] = *reinterpret_cast<const float4*>(hd + (size_t)tn * 40 + (j + 8) * 4);
        wv[1] = __ldg(reinterpret_cast<const float4*>(attn + (j + 8) * 4));
    }

    float part = 0.f, x;
    x = av[0].x + bv[0].x; part = fmaf((x > 0.f ? x : 0.2f * x), wv[0].x, part);
    x = av[0].y + bv[0].y; part = fmaf((x > 0.f ? x : 0.2f * x), wv[0].y, part);
    x = av[0].z + bv[0].z; part = fmaf((x > 0.f ? x : 0.2f * x), wv[0].z, part);
    x = av[0].w + bv[0].w; part = fmaf((x > 0.f ? x : 0.2f * x), wv[0].w, part);
    if (act2) {
        x = av[1].x + bv[1].x; part = fmaf((x > 0.f ? x : 0.2f * x), wv[1].x, part);
        x = av[1].y + bv[1].y; part = fmaf((x > 0.f ? x : 0.2f * x), wv[1].y, part);
        x = av[1].z + bv[1].z; part = fmaf((x > 0.f ? x : 0.2f * x), wv[1].z, part);
        x = av[1].w + bv[1].w; part = fmaf((x > 0.f ? x : 0.2f * x), wv[1].w, part);
    }
    part += __shfl_xor_sync(0xffffffffu, part, 4);
    part += __shfl_xor_sync(0xffffffffu, part, 2);
    part += __shfl_xor_sync(0xffffffffu, part, 1);
    float p = __expf(part);

    float* o = out + (size_t)tn * 40;
    redv4(o + j * 4, p * av[0].x, p * av[0].y, p * av[0].z, p * av[0].w);
    if (act2)
        redv4(o + (j + 8) * 4, p * av[1].x, p * av[1].y, p * av[1].z, p * av[1].w);
    if (j == 0)
        red1(s + tn, p);
}

// ---- scale2: out = acc / (s + eps) ----
__global__ void k_scale2(float* __restrict__ out, const float* __restrict__ s) {
    int i = blockIdx.x * blockDim.x + threadIdx.x;
    if (i >= NN * 10) return;                        // FIX: bounds guard
    int t = i / 10, q = i - t * 10;
    float inv = 1.f / (__ldg(s + t) + 1e-9f);
    float4 v = *reinterpret_cast<float4*>(out + (size_t)t * 40 + q * 4);
    v.x *= inv; v.y *= inv; v.z *= inv; v.w *= inv;
    *reinterpret_cast<float4*>(out + (size_t)t * 40 + q * 4) = v;
}

// ================= launch =================
extern "C" void kernel_launch(void* const* d_in, const int* in_sizes, int n_in,
                              void* d_out, int out_size) {
    const float* x   = (const float*)d_in[0];
    const int*   src = (const int*)d_in[1];
    const int*   dst = (const int*)d_in[2];
    const float* W1s = (const float*)d_in[3];
    const float* b1s = (const float*)d_in[4];
    const float* W1d = (const float*)d_in[5];
    const float* b1d = (const float*)d_in[6];
    const float* a1  = (const float*)d_in[7];
    const float* W2s = (const float*)d_in[8];
    const float* b2s = (const float*)d_in[9];
    const float* W2d = (const float*)d_in[10];
    const float* b2d = (const float*)d_in[11];
    const float* a2  = (const float*)d_in[12];
    float* out = (float*)d_out;

    float *hs1, *hd1, *s1, *h1, *hs2, *hd2, *s2;
    cudaGetSymbolAddress((void**)&hs1, g_hs1);
    cudaGetSymbolAddress((void**)&hd1, g_hd1);
    cudaGetSymbolAddress((void**)&s1,  g_s1);
    cudaGetSymbolAddress((void**)&h1,  g_h1);
    cudaGetSymbolAddress((void**)&hs2, g_hs2);
    cudaGetSymbolAddress((void**)&hd2, g_hd2);
    cudaGetSymbolAddress((void**)&s2,  g_s2);

    const int T = 256;

    // launches 1-3: zero-init (gemm1 is launch #4 -> profiled)
    k_zero2<<<(NN * FF1 + T - 1) / T, T>>>(h1, NN * FF1, s1, NN * 8);
    k_zero1<<<(NN + T - 1) / T, T>>>(s2, NN);
    k_zero1<<<(NN * DD2 + T - 1) / T, T>>>(out, NN * DD2);

    // ---- layer 1 ----
    k_gemm1_mma<<<(NN + 127) / 128, 256>>>(x, W1s, b1s, W1d, b1d, hs1, hd1);   // #4
    k_edge_agg1<<<EE * 8 / T, T>>>(hs1, hd1, a1, src, dst, s1, h1);
    k_scale1<<<(NN * 16 + T - 1) / T, T>>>(h1, s1);

    // ---- layer 2 ----
    k_gemm_dual<<<NN / 32, dim3(64, 4)>>>(h1, FF1, DD2, W2s, b2s, W2d, b2d, hs2, hd2);
    k_edge_agg2<<<EE * 8 / T, T>>>(hs2, hd2, a2, src, dst, s2, out);
    k_scale2<<<(NN * 10 + T - 1) / T, T>>>(out, s2);
}

// round 7
// speedup vs baseline: 1.4911x; 1.1911x over previous
#include <cuda_runtime.h>
#include <math.h>

#define NN 100000
#define EE 1600000
#define F_IN 512
#define FF1 64
#define DD2 40

// ---------------- scratch ----------------
__device__ float g_hs1[NN * FF1];
__device__ float g_hd1[NN * FF1];
__device__ float g_s1[NN * 8];
__device__ float g_h1[NN * FF1];
__device__ float g_hs2[NN * DD2];
__device__ float g_hd2[NN * DD2];
__device__ float g_s2[NN];

// ---------------- PTX helpers ----------------
__device__ __forceinline__ unsigned f2tf32(float f) {
    unsigned u;
    asm("cvt.rna.tf32.f32 %0, %1;" : "=r"(u) : "f"(f));
    return u;
}
__device__ __forceinline__ void redv4(float* addr, float a, float b, float c, float d) {
    asm volatile("red.global.add.v4.f32 [%0], {%1,%2,%3,%4};"
                 :: "l"(addr), "f"(a), "f"(b), "f"(c), "f"(d) : "memory");
}
__device__ __forceinline__ void red1(float* addr, float a) {
    asm volatile("red.global.add.f32 [%0], %1;" :: "l"(addr), "f"(a) : "memory");
}
__device__ __forceinline__ void mma_tf32(float* acc, const unsigned* a, const unsigned* b) {
    asm volatile(
        "mma.sync.aligned.m16n8k8.row.col.f32.tf32.tf32.f32 "
        "{%0,%1,%2,%3}, {%4,%5,%6,%7}, {%8,%9}, {%0,%1,%2,%3};"
        : "+f"(acc[0]), "+f"(acc[1]), "+f"(acc[2]), "+f"(acc[3])
        : "r"(a[0]), "r"(a[1]), "r"(a[2]), "r"(a[3]), "r"(b[0]), "r"(b[1]));
}
__device__ __forceinline__ void cp_async16(void* smem_dst, const void* gsrc) {
    unsigned saddr = (unsigned)__cvta_generic_to_shared(smem_dst);
    asm volatile("cp.async.cg.shared.global [%0], [%1], 16;" :: "r"(saddr), "l"(gsrc));
}
__device__ __forceinline__ void cp_commit() { asm volatile("cp.async.commit_group;"); }
__device__ __forceinline__ void cp_wait0() { asm volatile("cp.async.wait_group 0;"); }

// ---------------- zero kernels ----------------
__global__ void k_zero2(float* a, int na, float* b, int nb) {
    int i = blockIdx.x * blockDim.x + threadIdx.x;
    if (i < na) a[i] = 0.f;
    if (i < nb) b[i] = 0.f;
}
__global__ void k_zero1(float* a, int na) {
    int i = blockIdx.x * blockDim.x + threadIdx.x;
    if (i < na) a[i] = 0.f;
}

// ================= layer-1 GEMM: tf32 mma, cp.async, 2 CTAs/SM =================
// BM=64, BN=128 (C1 cols 0..63 | C2 cols 64..127), BK=16.
// 8 warps: 2 (m) x 4 (n); warp tile 32x32 (mi=2 m16-tiles, ni=4 n8-tiles).
#define BM 64
#define BK 16
#define APAD2 20
#define BPAD2 136
__global__ __launch_bounds__(256, 2)
void k_gemm1_mma(const float* __restrict__ A,
                 const float* __restrict__ W1, const float* __restrict__ b1,
                 const float* __restrict__ W2, const float* __restrict__ b2,
                 float* __restrict__ C1, float* __restrict__ C2) {
    __shared__ float As[2][BM * APAD2];
    __shared__ float Bs[2][BK * BPAD2];

    const int tid = threadIdx.x;
    const int lane = tid & 31, warp = tid >> 5;
    const int wr = warp & 1, wc = warp >> 1;
    const int g = lane >> 2, tg = lane & 3;
    const int row0 = blockIdx.x * BM;

    float acc[2][4][4];
#pragma unroll
    for (int mi = 0; mi < 2; mi++)
#pragma unroll
        for (int ni = 0; ni < 4; ni++)
#pragma unroll
            for (int r = 0; r < 4; r++) acc[mi][ni][r] = 0.f;

    // A copy mapping: thread -> one float4: row rA (0..63), quad qA (0..3)
    const int rA = tid >> 2, qA = tid & 3;
    const int rAg = min(row0 + rA, NN - 1);
    const float* gA = A + (size_t)rAg * F_IN + qA * 4;
    const int sAoff = rA * APAD2 + qA * 4;

    // B copy mapping: thread -> two float4: (k=kB, c) and (k=kB+8, c)
    const int kB = tid >> 5;
    const int cB = (tid & 31) * 4;
    const float* gBsrc = (cB < 64) ? (W1 + kB * 64 + cB) : (W2 + kB * 64 + cB - 64);
    const int sBoff0 = kB * BPAD2 + cB;
    const int sBoff1 = (kB + 8) * BPAD2 + cB;

    auto issue = [&](int it, int buf) {
        const int kc = it * BK;
        cp_async16(&As[buf][sAoff], gA + kc);
        cp_async16(&Bs[buf][sBoff0], gBsrc + kc * 64);
        cp_async16(&Bs[buf][sBoff1], gBsrc + (kc + 8) * 64);
        cp_commit();
    };

    issue(0, 0);
    int buf = 0;
    const int NITER = F_IN / BK;   // 32
    for (int it = 0; it < NITER; it++) {
        cp_wait0();
        __syncthreads();
        if (it + 1 < NITER) issue(it + 1, buf ^ 1);

#pragma unroll
        for (int ks = 0; ks < 2; ks++) {
            const int k0 = ks * 8;
            unsigned afr[2][4], bfr[4][2];
#pragma unroll
            for (int mi = 0; mi < 2; mi++) {
                const int base = wr * 32 + mi * 16;
                afr[mi][0] = f2tf32(As[buf][(base + g) * APAD2 + k0 + tg]);
                afr[mi][1] = f2tf32(As[buf][(base + g + 8) * APAD2 + k0 + tg]);
                afr[mi][2] = f2tf32(As[buf][(base + g) * APAD2 + k0 + tg + 4]);
                afr[mi][3] = f2tf32(As[buf][(base + g + 8) * APAD2 + k0 + tg + 4]);
            }
#pragma unroll
            for (int ni = 0; ni < 4; ni++) {
                const int col = wc * 32 + ni * 8 + g;
                bfr[ni][0] = f2tf32(Bs[buf][(k0 + tg) * BPAD2 + col]);
                bfr[ni][1] = f2tf32(Bs[buf][(k0 + tg + 4) * BPAD2 + col]);
            }
#pragma unroll
            for (int mi = 0; mi < 2; mi++)
#pragma unroll
                for (int ni = 0; ni < 4; ni++)
                    mma_tf32(acc[mi][ni], afr[mi], bfr[ni]);
        }
        buf ^= 1;
    }

    // epilogue
    float* Cw = (wc < 2) ? C1 : C2;
    const float* bw = (wc < 2) ? b1 : b2;
    const int cbase = (wc < 2) ? wc * 32 : (wc - 2) * 32;
#pragma unroll
    for (int mi = 0; mi < 2; mi++) {
#pragma unroll
        for (int ni = 0; ni < 4; ni++) {
            const int col = cbase + ni * 8 + 2 * tg;
            const float bb0 = __ldg(bw + col), bb1 = __ldg(bw + col + 1);
            const int r0 = row0 + wr * 32 + mi * 16 + g;
            const int r1 = r0 + 8;
            if (r0 < NN) {
                float2 v = make_float2(acc[mi][ni][0] + bb0, acc[mi][ni][1] + bb1);
                *reinterpret_cast<float2*>(Cw + (size_t)r0 * 64 + col) = v;
            }
            if (r1 < NN) {
                float2 v = make_float2(acc[mi][ni][2] + bb0, acc[mi][ni][3] + bb1);
                *reinterpret_cast<float2*>(Cw + (size_t)r1 * 64 + col) = v;
            }
        }
    }
}

// ================= layer-2 GEMM (FFMA, K=64, M=40) =================
__global__ void k_gemm_dual(const float* __restrict__ A, int K, int M,
                            const float* __restrict__ W1, const float* __restrict__ b1,
                            const float* __restrict__ W2, const float* __restrict__ b2,
                            float* __restrict__ C1, float* __restrict__ C2) {
    __shared__ float xs[32][16];
    __shared__ float w1s[16][64];
    __shared__ float w2s[16][64];
    const int tx = threadIdx.x;
    const int ty = threadIdx.y;
    const int tid = ty * 64 + tx;
    const int row0 = blockIdx.x * 32;

    float acc1[8], acc2[8];
#pragma unroll
    for (int r = 0; r < 8; r++) { acc1[r] = 0.f; acc2[r] = 0.f; }

    for (int kc = 0; kc < K; kc += 16) {
        for (int i = tid; i < 32 * 16; i += 256) {
            int r = i >> 4, k = i & 15;
            xs[r][k] = A[(row0 + r) * K + kc + k];
        }
        for (int i = tid; i < 16 * 64; i += 256) {
            int k = i >> 6, c = i & 63;
            float v1 = 0.f, v2 = 0.f;
            if (c < M) { v1 = W1[(kc + k) * M + c]; v2 = W2[(kc + k) * M + c]; }
            w1s[k][c] = v1; w2s[k][c] = v2;
        }
        __syncthreads();
#pragma unroll
        for (int kk = 0; kk < 16; kk++) {
            float w1 = w1s[kk][tx], w2 = w2s[kk][tx];
#pragma unroll
            for (int r = 0; r < 8; r++) {
                float a = xs[ty * 8 + r][kk];
                acc1[r] = fmaf(a, w1, acc1[r]);
                acc2[r] = fmaf(a, w2, acc2[r]);
            }
        }
        __syncthreads();
    }

    if (tx < M) {
        float bb1 = b1[tx], bb2 = b2[tx];
#pragma unroll
        for (int r = 0; r < 8; r++) {
            int row = row0 + ty * 8 + r;
            C1[row * M + tx] = acc1[r] + bb1;
            C2[row * M + tx] = acc2[r] + bb2;
        }
    }
}

// ========== fused layer-1 edge pass: gather once, RED p and p*hs ==========
__global__ __launch_bounds__(256)
void k_edge_agg1(const float* __restrict__ hs, const float* __restrict__ hd,
                 const float* __restrict__ attn,
                 const int* __restrict__ src, const int* __restrict__ dst,
                 float* __restrict__ s, float* __restrict__ acc) {
    int idx = blockIdx.x * blockDim.x + threadIdx.x;   // EE*8 exact
    int e = idx >> 3, h = idx & 7;
    int sn = __ldg(src + e), tn = __ldg(dst + e);
    const float4* a = reinterpret_cast<const float4*>(hs + (size_t)sn * 64 + h * 8);
    const float4* b = reinterpret_cast<const float4*>(hd + (size_t)tn * 64 + h * 8);
    const float4* w = reinterpret_cast<const float4*>(attn + h * 8);
    float4 a0 = a[0], a1 = a[1];
    float4 b0 = b[0], b1 = b[1];
    float4 w0 = __ldg(&w[0]), w1 = __ldg(&w[1]);

    float lg = 0.f, x;
    x = a0.x + b0.x; lg = fmaf((x > 0.f ? x : 0.2f * x), w0.x, lg);
    x = a0.y + b0.y; lg = fmaf((x > 0.f ? x : 0.2f * x), w0.y, lg);
    x = a0.z + b0.z; lg = fmaf((x > 0.f ? x : 0.2f * x), w0.z, lg);
    x = a0.w + b0.w; lg = fmaf((x > 0.f ? x : 0.2f * x), w0.w, lg);
    x = a1.x + b1.x; lg = fmaf((x > 0.f ? x : 0.2f * x), w1.x, lg);
    x = a1.y + b1.y; lg = fmaf((x > 0.f ? x : 0.2f * x), w1.y, lg);
    x = a1.z + b1.z; lg = fmaf((x > 0.f ? x : 0.2f * x), w1.z, lg);
    x = a1.w + b1.w; lg = fmaf((x > 0.f ? x : 0.2f * x), w1.w, lg);

    float p = __expf(lg);

    float* o = acc + (size_t)tn * 64 + h * 8;
    redv4(o,     p * a0.x, p * a0.y, p * a0.z, p * a0.w);
    redv4(o + 4, p * a1.x, p * a1.y, p * a1.z, p * a1.w);

    float p1 = __shfl_down_sync(0xffffffffu, p, 1);
    float p2 = __shfl_down_sync(0xffffffffu, p, 2);
    float p3 = __shfl_down_sync(0xffffffffu, p, 3);
    if ((h & 3) == 0)
        redv4(s + (size_t)tn * 8 + h, p, p1, p2, p3);
}

// ---- scale1: h1 = elu(acc / (s + eps)) ----
__global__ void k_scale1(float* __restrict__ acc, const float* __restrict__ s) {
    int i = blockIdx.x * blockDim.x + threadIdx.x;
    if (i >= NN * 16) return;
    int t = i >> 4, q = i & 15;
    float inv = 1.f / (__ldg(s + t * 8 + (q >> 1)) + 1e-9f);
    float4 v = *reinterpret_cast<float4*>(acc + (size_t)t * 64 + q * 4);
    v.x *= inv; v.y *= inv; v.z *= inv; v.w *= inv;
    v.x = v.x > 0.f ? v.x : (__expf(v.x) - 1.f);
    v.y = v.y > 0.f ? v.y : (__expf(v.y) - 1.f);
    v.z = v.z > 0.f ? v.z : (__expf(v.z) - 1.f);
    v.w = v.w > 0.f ? v.w : (__expf(v.w) - 1.f);
    *reinterpret_cast<float4*>(acc + (size_t)t * 64 + q * 4) = v;
}

// ========== fused layer-2 edge pass ==========
__global__ __launch_bounds__(256)
void k_edge_agg2(const float* __restrict__ hs, const float* __restrict__ hd,
                 const float* __restrict__ attn,
                 const int* __restrict__ src, const int* __restrict__ dst,
                 float* __restrict__ s, float* __restrict__ out) {
    int idx = blockIdx.x * blockDim.x + threadIdx.x;   // EE*8 exact
    int e = idx >> 3, j = idx & 7;
    int sn = __ldg(src + e), tn = __ldg(dst + e);

    float4 av[2], bv[2], wv[2];
    bool act2 = (j < 2);
    av[0] = *reinterpret_cast<const float4*>(hs + (size_t)sn * 40 + j * 4);
    bv[0] = *reinterpret_cast<const float4*>(hd + (size_t)tn * 40 + j * 4);
    wv[0] = __ldg(reinterpret_cast<const float4*>(attn + j * 4));
    if (act2) {
        av[1] = *reinterpret_cast<const float4*>(hs + (size_t)sn * 40 + (j + 8) * 4);
        bv[1] = *reinterpret_cast<const float4*>(hd + (size_t)tn * 40 + (j + 8) * 4);
        wv[1] = __ldg(reinterpret_cast<const float4*>(attn + (j + 8) * 4));
    }

    float part = 0.f, x;
    x = av[0].x + bv[0].x; part = fmaf((x > 0.f ? x : 0.2f * x), wv[0].x, part);
    x = av[0].y + bv[0].y; part = fmaf((x > 0.f ? x : 0.2f * x), wv[0].y, part);
    x = av[0].z + bv[0].z; part = fmaf((x > 0.f ? x : 0.2f * x), wv[0].z, part);
    x = av[0].w + bv[0].w; part = fmaf((x > 0.f ? x : 0.2f * x), wv[0].w, part);
    if (act2) {
        x = av[1].x + bv[1].x; part = fmaf((x > 0.f ? x : 0.2f * x), wv[1].x, part);
        x = av[1].y + bv[1].y; part = fmaf((x > 0.f ? x : 0.2f * x), wv[1].y, part);
        x = av[1].z + bv[1].z; part = fmaf((x > 0.f ? x : 0.2f * x), wv[1].z, part);
        x = av[1].w + bv[1].w; part = fmaf((x > 0.f ? x : 0.2f * x), wv[1].w, part);
    }
    part += __shfl_xor_sync(0xffffffffu, part, 4);
    part += __shfl_xor_sync(0xffffffffu, part, 2);
    part += __shfl_xor_sync(0xffffffffu, part, 1);
    float p = __expf(part);

    float* o = out + (size_t)tn * 40;
    redv4(o + j * 4, p * av[0].x, p * av[0].y, p * av[0].z, p * av[0].w);
    if (act2)
        redv4(o + (j + 8) * 4, p * av[1].x, p * av[1].y, p * av[1].z, p * av[1].w);
    if (j == 0)
        red1(s + tn, p);
}

// ---- scale2: out = acc / (s + eps) ----
__global__ void k_scale2(float* __restrict__ out, const float* __restrict__ s) {
    int i = blockIdx.x * blockDim.x + threadIdx.x;
    if (i >= NN * 10) return;
    int t = i / 10, q = i - t * 10;
    float inv = 1.f / (__ldg(s + t) + 1e-9f);
    float4 v = *reinterpret_cast<float4*>(out + (size_t)t * 40 + q * 4);
    v.x *= inv; v.y *= inv; v.z *= inv; v.w *= inv;
    *reinterpret_cast<float4*>(out + (size_t)t * 40 + q * 4) = v;
}

// ================= launch =================
extern "C" void kernel_launch(void* const* d_in, const int* in_sizes, int n_in,
                              void* d_out, int out_size) {
    const float* x   = (const float*)d_in[0];
    const int*   src = (const int*)d_in[1];
    const int*   dst = (const int*)d_in[2];
    const float* W1s = (const float*)d_in[3];
    const float* b1s = (const float*)d_in[4];
    const float* W1d = (const float*)d_in[5];
    const float* b1d = (const float*)d_in[6];
    const float* a1  = (const float*)d_in[7];
    const float* W2s = (const float*)d_in[8];
    const float* b2s = (const float*)d_in[9];
    const float* W2d = (const float*)d_in[10];
    const float* b2d = (const float*)d_in[11];
    const float* a2  = (const float*)d_in[12];
    float* out = (float*)d_out;

    float *hs1, *hd1, *s1, *h1, *hs2, *hd2, *s2;
    cudaGetSymbolAddress((void**)&hs1, g_hs1);
    cudaGetSymbolAddress((void**)&hd1, g_hd1);
    cudaGetSymbolAddress((void**)&s1,  g_s1);
    cudaGetSymbolAddress((void**)&h1,  g_h1);
    cudaGetSymbolAddress((void**)&hs2, g_hs2);
    cudaGetSymbolAddress((void**)&hd2, g_hd2);
    cudaGetSymbolAddress((void**)&s2,  g_s2);

    const int T = 256;

    // launches 1-3: zero-init (gemm1 is launch #4 -> profiled)
    k_zero2<<<(NN * FF1 + T - 1) / T, T>>>(h1, NN * FF1, s1, NN * 8);
    k_zero1<<<(NN + T - 1) / T, T>>>(s2, NN);
    k_zero1<<<(NN * DD2 + T - 1) / T, T>>>(out, NN * DD2);

    // ---- layer 1 ----
    k_gemm1_mma<<<(NN + BM - 1) / BM, 256>>>(x, W1s, b1s, W1d, b1d, hs1, hd1);  // #4
    k_edge_agg1<<<EE * 8 / T, T>>>(hs1, hd1, a1, src, dst, s1, h1);
    k_scale1<<<(NN * 16 + T - 1) / T, T>>>(h1, s1);

    // ---- layer 2 ----
    k_gemm_dual<<<NN / 32, dim3(64, 4)>>>(h1, FF1, DD2, W2s, b2s, W2d, b2d, hs2, hd2);
    k_edge_agg2<<<EE * 8 / T, T>>>(hs2, hd2, a2, src, dst, s2, out);
    k_scale2<<<(NN * 10 + T - 1) / T, T>>>(out, s2);
}

// round 8
// speedup vs baseline: 1.5114x; 1.0136x over previous
#include <cuda_runtime.h>
#include <math.h>

#define NN 100000
#define EE 1600000
#define F_IN 512
#define FF1 64
#define DD2 40

// ---------------- scratch ----------------
__device__ float g_hs1[NN * FF1];
__device__ float g_hd1[NN * FF1];
__device__ float g_s1[NN * 8];
__device__ float g_h1[NN * FF1];
__device__ float g_hs2[NN * DD2];
__device__ float g_hd2[NN * DD2];
__device__ float g_s2[NN];

// ---------------- PTX helpers ----------------
__device__ __forceinline__ unsigned f2tf32(float f) {
    unsigned u;
    asm("cvt.rna.tf32.f32 %0, %1;" : "=r"(u) : "f"(f));
    return u;
}
__device__ __forceinline__ void redv4(float* addr, float a, float b, float c, float d) {
    asm volatile("red.global.add.v4.f32 [%0], {%1,%2,%3,%4};"
                 :: "l"(addr), "f"(a), "f"(b), "f"(c), "f"(d) : "memory");
}
__device__ __forceinline__ void red1(float* addr, float a) {
    asm volatile("red.global.add.f32 [%0], %1;" :: "l"(addr), "f"(a) : "memory");
}
__device__ __forceinline__ void mma_tf32(float* acc, const unsigned* a, const unsigned* b) {
    asm volatile(
        "mma.sync.aligned.m16n8k8.row.col.f32.tf32.tf32.f32 "
        "{%0,%1,%2,%3}, {%4,%5,%6,%7}, {%8,%9}, {%0,%1,%2,%3};"
        : "+f"(acc[0]), "+f"(acc[1]), "+f"(acc[2]), "+f"(acc[3])
        : "r"(a[0]), "r"(a[1]), "r"(a[2]), "r"(a[3]), "r"(b[0]), "r"(b[1]));
}
__device__ __forceinline__ void cp_async16(void* smem_dst, const void* gsrc) {
    unsigned saddr = (unsigned)__cvta_generic_to_shared(smem_dst);
    asm volatile("cp.async.cg.shared.global [%0], [%1], 16;" :: "r"(saddr), "l"(gsrc));
}
__device__ __forceinline__ void cp_commit() { asm volatile("cp.async.commit_group;"); }
__device__ __forceinline__ void cp_wait1() { asm volatile("cp.async.wait_group 1;"); }

// ---------------- zero kernels ----------------
__global__ void k_zero2(float* a, int na, float* b, int nb) {
    int i = blockIdx.x * blockDim.x + threadIdx.x;
    if (i < na) a[i] = 0.f;
    if (i < nb) b[i] = 0.f;
}
__global__ void k_zero1(float* a, int na) {
    int i = blockIdx.x * blockDim.x + threadIdx.x;
    if (i < na) a[i] = 0.f;
}

// ================= layer-1 GEMM: tf32 mma, 3-stage cp.async, 3 CTAs/SM ===========
// BM=64, BN=128 (C1 cols 0..63 | C2 cols 64..127), BK=16.
// 8 warps: 2 (m) x 4 (n); warp tile 32x32.
#define BM 64
#define BK 16
#define APAD2 20
#define BPAD2 136
#define NSTAGE 3
__global__ __launch_bounds__(256, 3)
void k_gemm1_mma(const float* __restrict__ A,
                 const float* __restrict__ W1, const float* __restrict__ b1,
                 const float* __restrict__ W2, const float* __restrict__ b2,
                 float* __restrict__ C1, float* __restrict__ C2) {
    __shared__ float As[NSTAGE][BM * APAD2];
    __shared__ float Bs[NSTAGE][BK * BPAD2];

    const int tid = threadIdx.x;
    const int lane = tid & 31, warp = tid >> 5;
    const int wr = warp & 1, wc = warp >> 1;
    const int g = lane >> 2, tg = lane & 3;
    const int row0 = blockIdx.x * BM;

    float acc[2][4][4];
#pragma unroll
    for (int mi = 0; mi < 2; mi++)
#pragma unroll
        for (int ni = 0; ni < 4; ni++)
#pragma unroll
            for (int r = 0; r < 4; r++) acc[mi][ni][r] = 0.f;

    // A copy mapping: thread -> one float4
    const int rA = tid >> 2, qA = tid & 3;
    const int rAg = min(row0 + rA, NN - 1);
    const float* gA = A + (size_t)rAg * F_IN + qA * 4;
    const int sAoff = rA * APAD2 + qA * 4;

    // B copy mapping: thread -> two float4
    const int kB = tid >> 5;
    const int cB = (tid & 31) * 4;
    const float* gBsrc = (cB < 64) ? (W1 + kB * 64 + cB) : (W2 + kB * 64 + cB - 64);
    const int sBoff0 = kB * BPAD2 + cB;
    const int sBoff1 = (kB + 8) * BPAD2 + cB;

    auto issue = [&](int it) {
        const int buf = it % NSTAGE;
        const int kc = it * BK;
        cp_async16(&As[buf][sAoff], gA + kc);
        cp_async16(&Bs[buf][sBoff0], gBsrc + kc * 64);
        cp_async16(&Bs[buf][sBoff1], gBsrc + (kc + 8) * 64);
        cp_commit();
    };

    const int NITER = F_IN / BK;   // 32
    issue(0);
    issue(1);
    for (int it = 0; it < NITER; it++) {
        cp_wait1();                 // buffer it%NSTAGE ready
        __syncthreads();
        if (it + 2 < NITER) issue(it + 2);
        else cp_commit();           // empty group keeps wait_group accounting exact
        const int buf = it % NSTAGE;

#pragma unroll
        for (int ks = 0; ks < 2; ks++) {
            const int k0 = ks * 8;
            unsigned afr[2][4], bfr[4][2];
#pragma unroll
            for (int mi = 0; mi < 2; mi++) {
                const int base = wr * 32 + mi * 16;
                afr[mi][0] = f2tf32(As[buf][(base + g) * APAD2 + k0 + tg]);
                afr[mi][1] = f2tf32(As[buf][(base + g + 8) * APAD2 + k0 + tg]);
                afr[mi][2] = f2tf32(As[buf][(base + g) * APAD2 + k0 + tg + 4]);
                afr[mi][3] = f2tf32(As[buf][(base + g + 8) * APAD2 + k0 + tg + 4]);
            }
#pragma unroll
            for (int ni = 0; ni < 4; ni++) {
                const int col = wc * 32 + ni * 8 + g;
                bfr[ni][0] = f2tf32(Bs[buf][(k0 + tg) * BPAD2 + col]);
                bfr[ni][1] = f2tf32(Bs[buf][(k0 + tg + 4) * BPAD2 + col]);
            }
#pragma unroll
            for (int mi = 0; mi < 2; mi++)
#pragma unroll
                for (int ni = 0; ni < 4; ni++)
                    mma_tf32(acc[mi][ni], afr[mi], bfr[ni]);
        }
    }

    // epilogue
    float* Cw = (wc < 2) ? C1 : C2;
    const float* bw = (wc < 2) ? b1 : b2;
    const int cbase = (wc < 2) ? wc * 32 : (wc - 2) * 32;
#pragma unroll
    for (int mi = 0; mi < 2; mi++) {
#pragma unroll
        for (int ni = 0; ni < 4; ni++) {
            const int col = cbase + ni * 8 + 2 * tg;
            const float bb0 = __ldg(bw + col), bb1 = __ldg(bw + col + 1);
            const int r0 = row0 + wr * 32 + mi * 16 + g;
            const int r1 = r0 + 8;
            if (r0 < NN) {
                float2 v = make_float2(acc[mi][ni][0] + bb0, acc[mi][ni][1] + bb1);
                *reinterpret_cast<float2*>(Cw + (size_t)r0 * 64 + col) = v;
            }
            if (r1 < NN) {
                float2 v = make_float2(acc[mi][ni][2] + bb0, acc[mi][ni][3] + bb1);
                *reinterpret_cast<float2*>(Cw + (size_t)r1 * 64 + col) = v;
            }
        }
    }
}

// ================= layer-2 GEMM (FFMA, K=64, M=40) =================
__global__ void k_gemm_dual(const float* __restrict__ A, int K, int M,
                            const float* __restrict__ W1, const float* __restrict__ b1,
                            const float* __restrict__ W2, const float* __restrict__ b2,
                            float* __restrict__ C1, float* __restrict__ C2) {
    __shared__ float xs[32][16];
    __shared__ float w1s[16][64];
    __shared__ float w2s[16][64];
    const int tx = threadIdx.x;
    const int ty = threadIdx.y;
    const int tid = ty * 64 + tx;
    const int row0 = blockIdx.x * 32;

    float acc1[8], acc2[8];
#pragma unroll
    for (int r = 0; r < 8; r++) { acc1[r] = 0.f; acc2[r] = 0.f; }

    for (int kc = 0; kc < K; kc += 16) {
        for (int i = tid; i < 32 * 16; i += 256) {
            int r = i >> 4, k = i & 15;
            xs[r][k] = A[(row0 + r) * K + kc + k];
        }
        for (int i = tid; i < 16 * 64; i += 256) {
            int k = i >> 6, c = i & 63;
            float v1 = 0.f, v2 = 0.f;
            if (c < M) { v1 = W1[(kc + k) * M + c]; v2 = W2[(kc + k) * M + c]; }
            w1s[k][c] = v1; w2s[k][c] = v2;
        }
        __syncthreads();
#pragma unroll
        for (int kk = 0; kk < 16; kk++) {
            float w1 = w1s[kk][tx], w2 = w2s[kk][tx];
#pragma unroll
            for (int r = 0; r < 8; r++) {
                float a = xs[ty * 8 + r][kk];
                acc1[r] = fmaf(a, w1, acc1[r]);
                acc2[r] = fmaf(a, w2, acc2[r]);
            }
        }
        __syncthreads();
    }

    if (tx < M) {
        float bb1 = b1[tx], bb2 = b2[tx];
#pragma unroll
        for (int r = 0; r < 8; r++) {
            int row = row0 + ty * 8 + r;
            C1[row * M + tx] = acc1[r] + bb1;
            C2[row * M + tx] = acc2[r] + bb2;
        }
    }
}

// ========== fused layer-1 edge pass: gather once, RED p and p*hs ==========
__global__ __launch_bounds__(256)
void k_edge_agg1(const float* __restrict__ hs, const float* __restrict__ hd,
                 const float* __restrict__ attn,
                 const int* __restrict__ src, const int* __restrict__ dst,
                 float* __restrict__ s, float* __restrict__ acc) {
    int idx = blockIdx.x * blockDim.x + threadIdx.x;   // EE*8 exact
    int e = idx >> 3, h = idx & 7;
    int sn = __ldg(src + e), tn = __ldg(dst + e);
    const float4* a = reinterpret_cast<const float4*>(hs + (size_t)sn * 64 + h * 8);
    const float4* b = reinterpret_cast<const float4*>(hd + (size_t)tn * 64 + h * 8);
    const float4* w = reinterpret_cast<const float4*>(attn + h * 8);
    float4 a0 = a[0], a1 = a[1];
    float4 b0 = b[0], b1 = b[1];
    float4 w0 = __ldg(&w[0]), w1 = __ldg(&w[1]);

    float lg = 0.f, x;
    x = a0.x + b0.x; lg = fmaf((x > 0.f ? x : 0.2f * x), w0.x, lg);
    x = a0.y + b0.y; lg = fmaf((x > 0.f ? x : 0.2f * x), w0.y, lg);
    x = a0.z + b0.z; lg = fmaf((x > 0.f ? x : 0.2f * x), w0.z, lg);
    x = a0.w + b0.w; lg = fmaf((x > 0.f ? x : 0.2f * x), w0.w, lg);
    x = a1.x + b1.x; lg = fmaf((x > 0.f ? x : 0.2f * x), w1.x, lg);
    x = a1.y + b1.y; lg = fmaf((x > 0.f ? x : 0.2f * x), w1.y, lg);
    x = a1.z + b1.z; lg = fmaf((x > 0.f ? x : 0.2f * x), w1.z, lg);
    x = a1.w + b1.w; lg = fmaf((x > 0.f ? x : 0.2f * x), w1.w, lg);

    float p = __expf(lg);

    float* o = acc + (size_t)tn * 64 + h * 8;
    redv4(o,     p * a0.x, p * a0.y, p * a0.z, p * a0.w);
    redv4(o + 4, p * a1.x, p * a1.y, p * a1.z, p * a1.w);

    float p1 = __shfl_down_sync(0xffffffffu, p, 1);
    float p2 = __shfl_down_sync(0xffffffffu, p, 2);
    float p3 = __shfl_down_sync(0xffffffffu, p, 3);
    if ((h & 3) == 0)
        redv4(s + (size_t)tn * 8 + h, p, p1, p2, p3);
}

// ---- scale1: h1 = elu(acc / (s + eps)) ----
__global__ void k_scale1(float* __restrict__ acc, const float* __restrict__ s) {
    int i = blockIdx.x * blockDim.x + threadIdx.x;
    if (i >= NN * 16) return;
    int t = i >> 4, q = i & 15;
    float inv = 1.f / (__ldg(s + t * 8 + (q >> 1)) + 1e-9f);
    float4 v = *reinterpret_cast<float4*>(acc + (size_t)t * 64 + q * 4);
    v.x *= inv; v.y *= inv; v.z *= inv; v.w *= inv;
    v.x = v.x > 0.f ? v.x : (__expf(v.x) - 1.f);
    v.y = v.y > 0.f ? v.y : (__expf(v.y) - 1.f);
    v.z = v.z > 0.f ? v.z : (__expf(v.z) - 1.f);
    v.w = v.w > 0.f ? v.w : (__expf(v.w) - 1.f);
    *reinterpret_cast<float4*>(acc + (size_t)t * 64 + q * 4) = v;
}

// ========== fused layer-2 edge pass ==========
__global__ __launch_bounds__(256)
void k_edge_agg2(const float* __restrict__ hs, const float* __restrict__ hd,
                 const float* __restrict__ attn,
                 const int* __restrict__ src, const int* __restrict__ dst,
                 float* __restrict__ s, float* __restrict__ out) {
    int idx = blockIdx.x * blockDim.x + threadIdx.x;   // EE*8 exact
    int e = idx >> 3, j = idx & 7;
    int sn = __ldg(src + e), tn = __ldg(dst + e);

    float4 av[2], bv[2], wv[2];
    bool act2 = (j < 2);
    av[0] = *reinterpret_cast<const float4*>(hs + (size_t)sn * 40 + j * 4);
    bv[0] = *reinterpret_cast<const float4*>(hd + (size_t)tn * 40 + j * 4);
    wv[0] = __ldg(reinterpret_cast<const float4*>(attn + j * 4));
    if (act2) {
        av[1] = *reinterpret_cast<const float4*>(hs + (size_t)sn * 40 + (j + 8) * 4);
        bv[1] = *reinterpret_cast<const float4*>(hd + (size_t)tn * 40 + (j + 8) * 4);
        wv[1] = __ldg(reinterpret_cast<const float4*>(attn + (j + 8) * 4));
    }

    float part = 0.f, x;
    x = av[0].x + bv[0].x; part = fmaf((x > 0.f ? x : 0.2f * x), wv[0].x, part);
    x = av[0].y + bv[0].y; part = fmaf((x > 0.f ? x : 0.2f * x), wv[0].y, part);
    x = av[0].z + bv[0].z; part = fmaf((x > 0.f ? x : 0.2f * x), wv[0].z, part);
    x = av[0].w + bv[0].w; part = fmaf((x > 0.f ? x : 0.2f * x), wv[0].w, part);
    if (act2) {
        x = av[1].x + bv[1].x; part = fmaf((x > 0.f ? x : 0.2f * x), wv[1].x, part);
        x = av[1].y + bv[1].y; part = fmaf((x > 0.f ? x : 0.2f * x), wv[1].y, part);
        x = av[1].z + bv[1].z; part = fmaf((x > 0.f ? x : 0.2f * x), wv[1].z, part);
        x = av[1].w + bv[1].w; part = fmaf((x > 0.f ? x : 0.2f * x), wv[1].w, part);
    }
    part += __shfl_xor_sync(0xffffffffu, part, 4);
    part += __shfl_xor_sync(0xffffffffu, part, 2);
    part += __shfl_xor_sync(0xffffffffu, part, 1);
    float p = __expf(part);

    float* o = out + (size_t)tn * 40;
    redv4(o + j * 4, p * av[0].x, p * av[0].y, p * av[0].z, p * av[0].w);
    if (act2)
        redv4(o + (j + 8) * 4, p * av[1].x, p * av[1].y, p * av[1].z, p * av[1].w);
    if (j == 0)
        red1(s + tn, p);
}

// ---- scale2: out = acc / (s + eps) ----
__global__ void k_scale2(float* __restrict__ out, const float* __restrict__ s) {
    int i = blockIdx.x * blockDim.x + threadIdx.x;
    if (i >= NN * 10) return;
    int t = i / 10, q = i - t * 10;
    float inv = 1.f / (__ldg(s + t) + 1e-9f);
    float4 v = *reinterpret_cast<float4*>(out + (size_t)t * 40 + q * 4);
    v.x *= inv; v.y *= inv; v.z *= inv; v.w *= inv;
    *reinterpret_cast<float4*>(out + (size_t)t * 40 + q * 4) = v;
}

// ================= launch =================
extern "C" void kernel_launch(void* const* d_in, const int* in_sizes, int n_in,
                              void* d_out, int out_size) {
    const float* x   = (const float*)d_in[0];
    const int*   src = (const int*)d_in[1];
    const int*   dst = (const int*)d_in[2];
    const float* W1s = (const float*)d_in[3];
    const float* b1s = (const float*)d_in[4];
    const float* W1d = (const float*)d_in[5];
    const float* b1d = (const float*)d_in[6];
    const float* a1  = (const float*)d_in[7];
    const float* W2s = (const float*)d_in[8];
    const float* b2s = (const float*)d_in[9];
    const float* W2d = (const float*)d_in[10];
    const float* b2d = (const float*)d_in[11];
    const float* a2  = (const float*)d_in[12];
    float* out = (float*)d_out;

    float *hs1, *hd1, *s1, *h1, *hs2, *hd2, *s2;
    cudaGetSymbolAddress((void**)&hs1, g_hs1);
    cudaGetSymbolAddress((void**)&hd1, g_hd1);
    cudaGetSymbolAddress((void**)&s1,  g_s1);
    cudaGetSymbolAddress((void**)&h1,  g_h1);
    cudaGetSymbolAddress((void**)&hs2, g_hs2);
    cudaGetSymbolAddress((void**)&hd2, g_hd2);
    cudaGetSymbolAddress((void**)&s2,  g_s2);

    const int T = 256;

    // launches 1-3: zero-init (gemm1 is launch #4 -> profiled)
    k_zero2<<<(NN * FF1 + T - 1) / T, T>>>(h1, NN * FF1, s1, NN * 8);
    k_zero1<<<(NN + T - 1) / T, T>>>(s2, NN);
    k_zero1<<<(NN * DD2 + T - 1) / T, T>>>(out, NN * DD2);

    // ---- layer 1 ----
    k_gemm1_mma<<<(NN + BM - 1) / BM, 256>>>(x, W1s, b1s, W1d, b1d, hs1, hd1);  // #4
    k_edge_agg1<<<EE * 8 / T, T>>>(hs1, hd1, a1, src, dst, s1, h1);
    k_scale1<<<(NN * 16 + T - 1) / T, T>>>(h1, s1);

    // ---- layer 2 ----
    k_gemm_dual<<<NN / 32, dim3(64, 4)>>>(h1, FF1, DD2, W2s, b2s, W2d, b2d, hs2, hd2);
    k_edge_agg2<<<EE * 8 / T, T>>>(hs2, hd2, a2, src, dst, s2, out);
    k_scale2<<<(NN * 10 + T - 1) / T, T>>>(out, s2);
}

// round 9
// speedup vs baseline: 1.6981x; 1.1235x over previous
#include <cuda_runtime.h>
#include <math.h>

#define NN 100000
#define EE 1600000
#define F_IN 512
#define FF1 64
#define DD2 40

// ---------------- scratch ----------------
__device__ float g_hs1[NN * FF1];
__device__ float g_hd1[NN * FF1];
__device__ float g_s1[NN * 8];
__device__ float g_h1[NN * FF1];
__device__ float g_hs2[NN * DD2];
__device__ float g_hd2[NN * DD2];
__device__ float g_s2[NN];

// ---------------- PTX helpers ----------------
__device__ __forceinline__ unsigned f2tf32(float f) {
    unsigned u;
    asm("cvt.rna.tf32.f32 %0, %1;" : "=r"(u) : "f"(f));
    return u;
}
__device__ __forceinline__ void redv4(float* addr, float a, float b, float c, float d) {
    asm volatile("red.global.add.v4.f32 [%0], {%1,%2,%3,%4};"
                 :: "l"(addr), "f"(a), "f"(b), "f"(c), "f"(d) : "memory");
}
__device__ __forceinline__ void red1(float* addr, float a) {
    asm volatile("red.global.add.f32 [%0], %1;" :: "l"(addr), "f"(a) : "memory");
}
__device__ __forceinline__ void mma_tf32(float* acc, const unsigned* a, const unsigned* b) {
    asm volatile(
        "mma.sync.aligned.m16n8k8.row.col.f32.tf32.tf32.f32 "
        "{%0,%1,%2,%3}, {%4,%5,%6,%7}, {%8,%9}, {%0,%1,%2,%3};"
        : "+f"(acc[0]), "+f"(acc[1]), "+f"(acc[2]), "+f"(acc[3])
        : "r"(a[0]), "r"(a[1]), "r"(a[2]), "r"(a[3]), "r"(b[0]), "r"(b[1]));
}
__device__ __forceinline__ void cp_async16(void* smem_dst, const void* gsrc) {
    unsigned saddr = (unsigned)__cvta_generic_to_shared(smem_dst);
    asm volatile("cp.async.cg.shared.global [%0], [%1], 16;" :: "r"(saddr), "l"(gsrc));
}
__device__ __forceinline__ void cp_commit() { asm volatile("cp.async.commit_group;"); }
__device__ __forceinline__ void cp_wait0() { asm volatile("cp.async.wait_group 0;"); }
__device__ __forceinline__ void cp_wait1() { asm volatile("cp.async.wait_group 1;"); }

// ---------------- zero kernels ----------------
__global__ void k_zero2(float* a, int na, float* b, int nb) {
    int i = blockIdx.x * blockDim.x + threadIdx.x;
    if (i < na) a[i] = 0.f;
    if (i < nb) b[i] = 0.f;
}

// ================= layer-1 GEMM: tf32 mma, 3-stage cp.async =================
#define BM 64
#define BK 16
#define APAD2 20
#define BPAD2 136
#define NSTAGE 3
__global__ __launch_bounds__(256, 3)
void k_gemm1_mma(const float* __restrict__ A,
                 const float* __restrict__ W1, const float* __restrict__ b1,
                 const float* __restrict__ W2, const float* __restrict__ b2,
                 float* __restrict__ C1, float* __restrict__ C2) {
    __shared__ float As[NSTAGE][BM * APAD2];
    __shared__ float Bs[NSTAGE][BK * BPAD2];

    const int tid = threadIdx.x;
    const int lane = tid & 31, warp = tid >> 5;
    const int wr = warp & 1, wc = warp >> 1;
    const int g = lane >> 2, tg = lane & 3;
    const int row0 = blockIdx.x * BM;

    float acc[2][4][4];
#pragma unroll
    for (int mi = 0; mi < 2; mi++)
#pragma unroll
        for (int ni = 0; ni < 4; ni++)
#pragma unroll
            for (int r = 0; r < 4; r++) acc[mi][ni][r] = 0.f;

    const int rA = tid >> 2, qA = tid & 3;
    const int rAg = min(row0 + rA, NN - 1);
    const float* gA = A + (size_t)rAg * F_IN + qA * 4;
    const int sAoff = rA * APAD2 + qA * 4;

    const int kB = tid >> 5;
    const int cB = (tid & 31) * 4;
    const float* gBsrc = (cB < 64) ? (W1 + kB * 64 + cB) : (W2 + kB * 64 + cB - 64);
    const int sBoff0 = kB * BPAD2 + cB;
    const int sBoff1 = (kB + 8) * BPAD2 + cB;

    auto issue = [&](int it) {
        const int buf = it % NSTAGE;
        const int kc = it * BK;
        cp_async16(&As[buf][sAoff], gA + kc);
        cp_async16(&Bs[buf][sBoff0], gBsrc + kc * 64);
        cp_async16(&Bs[buf][sBoff1], gBsrc + (kc + 8) * 64);
        cp_commit();
    };

    const int NITER = F_IN / BK;   // 32
    issue(0);
    issue(1);
    for (int it = 0; it < NITER; it++) {
        cp_wait1();
        __syncthreads();
        if (it + 2 < NITER) issue(it + 2);
        else cp_commit();
        const int buf = it % NSTAGE;

#pragma unroll
        for (int ks = 0; ks < 2; ks++) {
            const int k0 = ks * 8;
            unsigned afr[2][4], bfr[4][2];
#pragma unroll
            for (int mi = 0; mi < 2; mi++) {
                const int base = wr * 32 + mi * 16;
                afr[mi][0] = f2tf32(As[buf][(base + g) * APAD2 + k0 + tg]);
                afr[mi][1] = f2tf32(As[buf][(base + g + 8) * APAD2 + k0 + tg]);
                afr[mi][2] = f2tf32(As[buf][(base + g) * APAD2 + k0 + tg + 4]);
                afr[mi][3] = f2tf32(As[buf][(base + g + 8) * APAD2 + k0 + tg + 4]);
            }
#pragma unroll
            for (int ni = 0; ni < 4; ni++) {
                const int col = wc * 32 + ni * 8 + g;
                bfr[ni][0] = f2tf32(Bs[buf][(k0 + tg) * BPAD2 + col]);
                bfr[ni][1] = f2tf32(Bs[buf][(k0 + tg + 4) * BPAD2 + col]);
            }
#pragma unroll
            for (int mi = 0; mi < 2; mi++)
#pragma unroll
                for (int ni = 0; ni < 4; ni++)
                    mma_tf32(acc[mi][ni], afr[mi], bfr[ni]);
        }
    }

    float* Cw = (wc < 2) ? C1 : C2;
    const float* bw = (wc < 2) ? b1 : b2;
    const int cbase = (wc < 2) ? wc * 32 : (wc - 2) * 32;
#pragma unroll
    for (int mi = 0; mi < 2; mi++) {
#pragma unroll
        for (int ni = 0; ni < 4; ni++) {
            const int col = cbase + ni * 8 + 2 * tg;
            const float bb0 = __ldg(bw + col), bb1 = __ldg(bw + col + 1);
            const int r0 = row0 + wr * 32 + mi * 16 + g;
            const int r1 = r0 + 8;
            if (r0 < NN) {
                float2 v = make_float2(acc[mi][ni][0] + bb0, acc[mi][ni][1] + bb1);
                *reinterpret_cast<float2*>(Cw + (size_t)r0 * 64 + col) = v;
            }
            if (r1 < NN) {
                float2 v = make_float2(acc[mi][ni][2] + bb0, acc[mi][ni][3] + bb1);
                *reinterpret_cast<float2*>(Cw + (size_t)r1 * 64 + col) = v;
            }
        }
    }
}

// ================= layer-2 GEMM: tf32 mma (K=64, M=40 dual) =================
// BM2=128 rows, 8 warps: wr=warp&3 (m, 32 rows each), wc=warp>>2 (0=C1, 1=C2).
// Warp tile 32 x 40: mi=2 (m16), ni=5 (n8). BK=16, NITER=4, double buffer.
#define BM2 128
#define APAD3 20
#define BPW 88      // B smem row width: 80 cols (C1|C2) + 8 pad
__global__ __launch_bounds__(256, 2)
void k_gemm2_mma(const float* __restrict__ A,
                 const float* __restrict__ W1, const float* __restrict__ b1,
                 const float* __restrict__ W2, const float* __restrict__ b2,
                 float* __restrict__ C1, float* __restrict__ C2) {
    __shared__ float As[2][BM2 * APAD3];
    __shared__ float Bs[2][BK * BPW];

    const int tid = threadIdx.x;
    const int lane = tid & 31, warp = tid >> 5;
    const int wr = warp & 3, wc = warp >> 2;
    const int g = lane >> 2, tg = lane & 3;
    const int row0 = blockIdx.x * BM2;

    float acc[2][5][4];
#pragma unroll
    for (int mi = 0; mi < 2; mi++)
#pragma unroll
        for (int ni = 0; ni < 5; ni++)
#pragma unroll
            for (int r = 0; r < 4; r++) acc[mi][ni][r] = 0.f;

    // A copy: 128 rows x 16 k = 512 float4; thread does rows rA and rA+64
    const int rA = tid >> 2, qA = tid & 3;
    const int rAg0 = min(row0 + rA, NN - 1);
    const int rAg1 = min(row0 + rA + 64, NN - 1);
    const float* gA0 = A + (size_t)rAg0 * FF1 + qA * 4;
    const float* gA1 = A + (size_t)rAg1 * FF1 + qA * 4;
    const int sAoff0 = rA * APAD3 + qA * 4;
    const int sAoff1 = (rA + 64) * APAD3 + qA * 4;

    // B copy: 16 k x 80 cols = 320 float4; thread t does i=t (t<256) and i=256+t (t<64)
    const int i0 = tid;                 // k=i0/20, c4=i0%20
    const int kB0 = i0 / 20, c40 = i0 % 20;
    const int i1 = 256 + tid;           // valid if tid < 64
    const int kB1 = i1 / 20, c41 = i1 % 20;
    const int cB0 = c40 * 4, cB1 = c41 * 4;
    const float* gB0 = (cB0 < 40) ? (W1 + kB0 * 40 + cB0) : (W2 + kB0 * 40 + cB0 - 40);
    const float* gB1 = (cB1 < 40) ? (W1 + kB1 * 40 + cB1) : (W2 + kB1 * 40 + cB1 - 40);
    const int sB0 = kB0 * BPW + cB0;
    const int sB1 = kB1 * BPW + cB1;

    auto issue = [&](int it) {
        const int buf = it & 1;
        const int kc = it * BK;
        cp_async16(&As[buf][sAoff0], gA0 + kc);
        cp_async16(&As[buf][sAoff1], gA1 + kc);
        cp_async16(&Bs[buf][sB0], gB0 + kc * 40);
        if (tid < 64) cp_async16(&Bs[buf][sB1], gB1 + kc * 40);
        cp_commit();
    };

    const int NITER = FF1 / BK;   // 4
    issue(0);
    for (int it = 0; it < NITER; it++) {
        cp_wait0();
        __syncthreads();
        if (it + 1 < NITER) issue(it + 1);
        const int buf = it & 1;

#pragma unroll
        for (int ks = 0; ks < 2; ks++) {
            const int k0 = ks * 8;
            unsigned afr[2][4], bfr[5][2];
#pragma unroll
            for (int mi = 0; mi < 2; mi++) {
                const int base = wr * 32 + mi * 16;
                afr[mi][0] = f2tf32(As[buf][(base + g) * APAD3 + k0 + tg]);
                afr[mi][1] = f2tf32(As[buf][(base + g + 8) * APAD3 + k0 + tg]);
                afr[mi][2] = f2tf32(As[buf][(base + g) * APAD3 + k0 + tg + 4]);
                afr[mi][3] = f2tf32(As[buf][(base + g + 8) * APAD3 + k0 + tg + 4]);
            }
#pragma unroll
            for (int ni = 0; ni < 5; ni++) {
                const int col = wc * 40 + ni * 8 + g;
                bfr[ni][0] = f2tf32(Bs[buf][(k0 + tg) * BPW + col]);
                bfr[ni][1] = f2tf32(Bs[buf][(k0 + tg + 4) * BPW + col]);
            }
#pragma unroll
            for (int mi = 0; mi < 2; mi++)
#pragma unroll
                for (int ni = 0; ni < 5; ni++)
                    mma_tf32(acc[mi][ni], afr[mi], bfr[ni]);
        }
    }

    float* Cw = (wc == 0) ? C1 : C2;
    const float* bw = (wc == 0) ? b1 : b2;
#pragma unroll
    for (int mi = 0; mi < 2; mi++) {
#pragma unroll
        for (int ni = 0; ni < 5; ni++) {
            const int col = ni * 8 + 2 * tg;
            const float bb0 = __ldg(bw + col), bb1 = __ldg(bw + col + 1);
            const int r0 = row0 + wr * 32 + mi * 16 + g;
            const int r1 = r0 + 8;
            if (r0 < NN) {
                float2 v = make_float2(acc[mi][ni][0] + bb0, acc[mi][ni][1] + bb1);
                *reinterpret_cast<float2*>(Cw + (size_t)r0 * 40 + col) = v;
            }
            if (r1 < NN) {
                float2 v = make_float2(acc[mi][ni][2] + bb0, acc[mi][ni][3] + bb1);
                *reinterpret_cast<float2*>(Cw + (size_t)r1 * 40 + col) = v;
            }
        }
    }
}

// ========== fused layer-1 edge pass ==========
__global__ __launch_bounds__(256)
void k_edge_agg1(const float* __restrict__ hs, const float* __restrict__ hd,
                 const float* __restrict__ attn,
                 const int* __restrict__ src, const int* __restrict__ dst,
                 float* __restrict__ s, float* __restrict__ acc) {
    int idx = blockIdx.x * blockDim.x + threadIdx.x;   // EE*8 exact
    int e = idx >> 3, h = idx & 7;
    int sn = __ldg(src + e), tn = __ldg(dst + e);
    const float4* a = reinterpret_cast<const float4*>(hs + (size_t)sn * 64 + h * 8);
    const float4* b = reinterpret_cast<const float4*>(hd + (size_t)tn * 64 + h * 8);
    const float4* w = reinterpret_cast<const float4*>(attn + h * 8);
    float4 a0 = a[0], a1 = a[1];
    float4 b0 = b[0], b1 = b[1];
    float4 w0 = __ldg(&w[0]), w1 = __ldg(&w[1]);

    float lg = 0.f, x;
    x = a0.x + b0.x; lg = fmaf((x > 0.f ? x : 0.2f * x), w0.x, lg);
    x = a0.y + b0.y; lg = fmaf((x > 0.f ? x : 0.2f * x), w0.y, lg);
    x = a0.z + b0.z; lg = fmaf((x > 0.f ? x : 0.2f * x), w0.z, lg);
    x = a0.w + b0.w; lg = fmaf((x > 0.f ? x : 0.2f * x), w0.w, lg);
    x = a1.x + b1.x; lg = fmaf((x > 0.f ? x : 0.2f * x), w1.x, lg);
    x = a1.y + b1.y; lg = fmaf((x > 0.f ? x : 0.2f * x), w1.y, lg);
    x = a1.z + b1.z; lg = fmaf((x > 0.f ? x : 0.2f * x), w1.z, lg);
    x = a1.w + b1.w; lg = fmaf((x > 0.f ? x : 0.2f * x), w1.w, lg);

    float p = __expf(lg);

    float* o = acc + (size_t)tn * 64 + h * 8;
    redv4(o,     p * a0.x, p * a0.y, p * a0.z, p * a0.w);
    redv4(o + 4, p * a1.x, p * a1.y, p * a1.z, p * a1.w);

    float p1 = __shfl_down_sync(0xffffffffu, p, 1);
    float p2 = __shfl_down_sync(0xffffffffu, p, 2);
    float p3 = __shfl_down_sync(0xffffffffu, p, 3);
    if ((h & 3) == 0)
        redv4(s + (size_t)tn * 8 + h, p, p1, p2, p3);
}

// ---- scale1: h1 = elu(acc / (s + eps)) ----
__global__ void k_scale1(float* __restrict__ acc, const float* __restrict__ s) {
    int i = blockIdx.x * blockDim.x + threadIdx.x;
    if (i >= NN * 16) return;
    int t = i >> 4, q = i & 15;
    float inv = 1.f / (__ldg(s + t * 8 + (q >> 1)) + 1e-9f);
    float4 v = *reinterpret_cast<float4*>(acc + (size_t)t * 64 + q * 4);
    v.x *= inv; v.y *= inv; v.z *= inv; v.w *= inv;
    v.x = v.x > 0.f ? v.x : (__expf(v.x) - 1.f);
    v.y = v.y > 0.f ? v.y : (__expf(v.y) - 1.f);
    v.z = v.z > 0.f ? v.z : (__expf(v.z) - 1.f);
    v.w = v.w > 0.f ? v.w : (__expf(v.w) - 1.f);
    *reinterpret_cast<float4*>(acc + (size_t)t * 64 + q * 4) = v;
}

// ========== fused layer-2 edge pass ==========
__global__ __launch_bounds__(256)
void k_edge_agg2(const float* __restrict__ hs, const float* __restrict__ hd,
                 const float* __restrict__ attn,
                 const int* __restrict__ src, const int* __restrict__ dst,
                 float* __restrict__ s, float* __restrict__ out) {
    int idx = blockIdx.x * blockDim.x + threadIdx.x;   // EE*8 exact
    int e = idx >> 3, j = idx & 7;
    int sn = __ldg(src + e), tn = __ldg(dst + e);

    float4 av[2], bv[2], wv[2];
    bool act2 = (j < 2);
    av[0] = *reinterpret_cast<const float4*>(hs + (size_t)sn * 40 + j * 4);
    bv[0] = *reinterpret_cast<const float4*>(hd + (size_t)tn * 40 + j * 4);
    wv[0] = __ldg(reinterpret_cast<const float4*>(attn + j * 4));
    if (act2) {
        av[1] = *reinterpret_cast<const float4*>(hs + (size_t)sn * 40 + (j + 8) * 4);
        bv[1] = *reinterpret_cast<const float4*>(hd + (size_t)tn * 40 + (j + 8) * 4);
        wv[1] = __ldg(reinterpret_cast<const float4*>(attn + (j + 8) * 4));
    }

    float part = 0.f, x;
    x = av[0].x + bv[0].x; part = fmaf((x > 0.f ? x : 0.2f * x), wv[0].x, part);
    x = av[0].y + bv[0].y; part = fmaf((x > 0.f ? x : 0.2f * x), wv[0].y, part);
    x = av[0].z + bv[0].z; part = fmaf((x > 0.f ? x : 0.2f * x), wv[0].z, part);
    x = av[0].w + bv[0].w; part = fmaf((x > 0.f ? x : 0.2f * x), wv[0].w, part);
    if (act2) {
        x = av[1].x + bv[1].x; part = fmaf((x > 0.f ? x : 0.2f * x), wv[1].x, part);
        x = av[1].y + bv[1].y; part = fmaf((x > 0.f ? x : 0.2f * x), wv[1].y, part);
        x = av[1].z + bv[1].z; part = fmaf((x > 0.f ? x : 0.2f * x), wv[1].z, part);
        x = av[1].w + bv[1].w; part = fmaf((x > 0.f ? x : 0.2f * x), wv[1].w, part);
    }
    part += __shfl_xor_sync(0xffffffffu, part, 4);
    part += __shfl_xor_sync(0xffffffffu, part, 2);
    part += __shfl_xor_sync(0xffffffffu, part, 1);
    float p = __expf(part);

    float* o = out + (size_t)tn * 40;
    redv4(o + j * 4, p * av[0].x, p * av[0].y, p * av[0].z, p * av[0].w);
    if (act2)
        redv4(o + (j + 8) * 4, p * av[1].x, p * av[1].y, p * av[1].z, p * av[1].w);
    if (j == 0)
        red1(s + tn, p);
}

// ---- scale2: out = acc / (s + eps) ----
__global__ void k_scale2(float* __restrict__ out, const float* __restrict__ s) {
    int i = blockIdx.x * blockDim.x + threadIdx.x;
    if (i >= NN * 10) return;
    int t = i / 10, q = i - t * 10;
    float inv = 1.f / (__ldg(s + t) + 1e-9f);
    float4 v = *reinterpret_cast<float4*>(out + (size_t)t * 40 + q * 4);
    v.x *= inv; v.y *= inv; v.z *= inv; v.w *= inv;
    *reinterpret_cast<float4*>(out + (size_t)t * 40 + q * 4) = v;
}

// ================= launch =================
extern "C" void kernel_launch(void* const* d_in, const int* in_sizes, int n_in,
                              void* d_out, int out_size) {
    const float* x   = (const float*)d_in[0];
    const int*   src = (const int*)d_in[1];
    const int*   dst = (const int*)d_in[2];
    const float* W1s = (const float*)d_in[3];
    const float* b1s = (const float*)d_in[4];
    const float* W1d = (const float*)d_in[5];
    const float* b1d = (const float*)d_in[6];
    const float* a1  = (const float*)d_in[7];
    const float* W2s = (const float*)d_in[8];
    const float* b2s = (const float*)d_in[9];
    const float* W2d = (const float*)d_in[10];
    const float* b2d = (const float*)d_in[11];
    const float* a2  = (const float*)d_in[12];
    float* out = (float*)d_out;

    float *hs1, *hd1, *s1, *h1, *hs2, *hd2, *s2;
    cudaGetSymbolAddress((void**)&hs1, g_hs1);
    cudaGetSymbolAddress((void**)&hd1, g_hd1);
    cudaGetSymbolAddress((void**)&s1,  g_s1);
    cudaGetSymbolAddress((void**)&h1,  g_h1);
    cudaGetSymbolAddress((void**)&hs2, g_hs2);
    cudaGetSymbolAddress((void**)&hd2, g_hd2);
    cudaGetSymbolAddress((void**)&s2,  g_s2);

    const int T = 256;

    // #1: zero h1+s1 ; #2: gemm1 ; #3: zero s2+out ; #4: edge_agg1 (profiled)
    k_zero2<<<(NN * FF1 + T - 1) / T, T>>>(h1, NN * FF1, s1, NN * 8);
    k_gemm1_mma<<<(NN + BM - 1) / BM, 256>>>(x, W1s, b1s, W1d, b1d, hs1, hd1);
    k_zero2<<<(NN * DD2 + T - 1) / T, T>>>(out, NN * DD2, s2, NN);
    k_edge_agg1<<<EE * 8 / T, T>>>(hs1, hd1, a1, src, dst, s1, h1);          // #4
    k_scale1<<<(NN * 16 + T - 1) / T, T>>>(h1, s1);

    // ---- layer 2 ----
    k_gemm2_mma<<<(NN + BM2 - 1) / BM2, 256>>>(h1, W2s, b2s, W2d, b2d, hs2, hd2);
    k_edge_agg2<<<EE * 8 / T, T>>>(hs2, hd2, a2, src, dst, s2, out);
    k_scale2<<<(NN * 10 + T - 1) / T, T>>>(out, s2);
}